// round 12
// baseline (speedup 1.0000x reference)
#include <cuda_runtime.h>
#include <cuda_bf16.h>
#include <math.h>
#include <stdint.h>

#define BATCH 4096
#define B2    8192
#define NTILE 2080                  // triangular 128x128 tiles per branch
#define NTOT  (2 * NTILE)
#define CMB_BLOCKS 128              // 2 branches x 64 row tiles
#define PREP_BLOCKS 1024
#define GRID_P 444                  // persistent CTAs (3/SM)
#define LN2F 0.6931471805599453f
#define ROOT_S 2.68579135f          // sqrt(log2(e)/T) folded into operands
#define UBASE 8.0f                  // user-branch fixed basis (logits +-7.22)

#define TROW 144                    // 128B row + 16B pad
#define TILE_SM (128 * TROW)        // 18432 B
#define SMEM_REQ (3 * TILE_SM + 6144)   // A + B0 + B1 + sRow(2K) + sCol(4K)

__device__ __align__(256) __nv_bfloat16 g_Y[2][B2 * 64];  // hi-only rows (128B)
// partial (m, s) per row of each 128-row tile r:
//   idx in [r, 64): row-side partial from tile (r, ct) over 128 cols
//   idx in [64, 64+2r): col-side from tile (r', r), r'=(idx-64)>>1, 64-row half
__device__ float g_s[2][64][192][128];
__device__ float g_mv[2][64][192][128];
__device__ float g_lse_partial[CMB_BLOCKS];
__device__ float g_pos_partial[PREP_BLOCKS];
__device__ int   g_count = 0;

// ---------------------------------------------------------------------------
__device__ __forceinline__ uint32_t smem_u32(const void* p) {
    uint32_t a;
    asm("{ .reg .u64 t; cvta.to.shared.u64 t, %1; cvt.u32.u64 %0, t; }" : "=r"(a) : "l"(p));
    return a;
}
__device__ __forceinline__ float ex2(float x) {
    float y; asm("ex2.approx.f32 %0, %1;" : "=f"(y) : "f"(x)); return y;
}
__device__ __forceinline__ float lg2(float x) {
    float y; asm("lg2.approx.f32 %0, %1;" : "=f"(y) : "f"(x)); return y;
}
__device__ __forceinline__ void ldsm4(uint32_t* r, uint32_t addr) {
    asm volatile("ldmatrix.sync.aligned.m8n8.x4.shared.b16 {%0,%1,%2,%3}, [%4];"
        : "=r"(r[0]), "=r"(r[1]), "=r"(r[2]), "=r"(r[3]) : "r"(addr));
}
__device__ __forceinline__ void mma16816(float* c, const uint32_t* a,
                                         uint32_t b0, uint32_t b1) {
    asm volatile("mma.sync.aligned.m16n8k16.row.col.f32.bf16.bf16.f32 "
        "{%0,%1,%2,%3}, {%4,%5,%6,%7}, {%8,%9}, {%0,%1,%2,%3};"
        : "+f"(c[0]), "+f"(c[1]), "+f"(c[2]), "+f"(c[3])
        : "r"(a[0]), "r"(a[1]), "r"(a[2]), "r"(a[3]), "r"(b0), "r"(b1));
}
#define CP16(dst, src) \
    asm volatile("cp.async.cg.shared.global [%0], [%1], 16;" :: "r"(dst), "l"(src))
#define CP_COMMIT() asm volatile("cp.async.commit_group;" ::: "memory")
#define CP_WAIT0()  asm volatile("cp.async.wait_group 0;" ::: "memory")

// ---------------------------------------------------------------------------
// Prep (unchanged from R11)
// ---------------------------------------------------------------------------
__global__ void __launch_bounds__(256) prep_kernel(
    const int* __restrict__ u_list, const int* __restrict__ i_list,
    const float* __restrict__ u1t, const float* __restrict__ i1t,
    const float* __restrict__ u2t, const float* __restrict__ i2t)
{
    int w      = blockIdx.x * 8 + (threadIdx.x >> 5);
    int lane   = threadIdx.x & 31;
    int branch = w >> 12;
    int i      = w & (BATCH - 1);

    int idx = (branch ? i_list : u_list)[i];
    const float* t1 = branch ? i1t : u1t;
    const float* t2 = branch ? i2t : u2t;

    float2 a = ((const float2*)(t1 + (size_t)idx * 64))[lane];
    float2 b = ((const float2*)(t2 + (size_t)idx * 64))[lane];

    if (branch == 0) {
        float na = a.x * a.x + a.y * a.y;
        float nb = b.x * b.x + b.y * b.y;
        #pragma unroll
        for (int o = 16; o; o >>= 1) {
            na += __shfl_xor_sync(0xffffffffu, na, o);
            nb += __shfl_xor_sync(0xffffffffu, nb, o);
        }
        float ia = rsqrtf(na), ib = rsqrtf(nb);
        a.x *= ia; a.y *= ia;
        b.x *= ib; b.y *= ib;
    }

    float pd = a.x * b.x + a.y * b.y;
    #pragma unroll
    for (int o = 16; o; o >>= 1) pd += __shfl_xor_sync(0xffffffffu, pd, o);

    __nv_bfloat16* Y = g_Y[branch];
    #pragma unroll
    for (int which = 0; which < 2; which++) {
        float2 v = which ? b : a;
        int row  = which ? (BATCH + i) : i;
        __nv_bfloat16 hx = __float2bfloat16(v.x * ROOT_S);
        __nv_bfloat16 hy = __float2bfloat16(v.y * ROOT_S);
        ((__nv_bfloat162*)(Y + (size_t)row * 64))[lane] = __nv_bfloat162(hx, hy);
    }

    __shared__ float sp_[8];
    if (lane == 0) sp_[threadIdx.x >> 5] = pd;
    __syncthreads();
    if (threadIdx.x == 0) {
        float s = 0.f;
        #pragma unroll
        for (int k = 0; k < 8; k++) s += sp_[k];
        g_pos_partial[blockIdx.x] = s;
    }
}

// ---------------------------------------------------------------------------
__device__ __forceinline__ void stage_tile(uint32_t sdst,
                                           const __nv_bfloat16* __restrict__ Y,
                                           int row0, int tid)
{
    #pragma unroll
    for (int i = 0; i < 4; i++) {
        int l   = i * 256 + tid;
        int row = l >> 3;
        int col = l & 7;
        uint32_t dst = sdst + (uint32_t)(row * TROW + col * 16);
        const char* src = (const char*)(Y + (size_t)(row0 + row) * 64) + col * 16;
        CP16(dst, src);
    }
}

// hi*hi half-mainloop: warp tile 32m x 32n, acc[mf(2)][nf(4)][4].
__device__ __forceinline__ void mainloop_half(float acc[2][4][4],
                                              uint32_t aAddr, uint32_t bAddr)
{
    #pragma unroll
    for (int kk = 0; kk < 4; kk++) {
        uint32_t ah[2][4];
        ldsm4(ah[0], aAddr + kk * 32);
        ldsm4(ah[1], aAddr + 16 * TROW + kk * 32);
        #pragma unroll
        for (int ng = 0; ng < 2; ng++) {
            uint32_t bh[4];
            ldsm4(bh, bAddr + ng * 16 * TROW + kk * 32);
            #pragma unroll
            for (int mf = 0; mf < 2; mf++) {
                mma16816(acc[mf][ng * 2],     ah[mf], bh[0], bh[1]);
                mma16816(acc[mf][ng * 2 + 1], ah[mf], bh[2], bh[3]);
            }
        }
    }
}

__device__ __forceinline__ void decode_tile(int t, int& r, int& c)
{
    r = (int)((129.0f - sqrtf(16641.0f - 8.0f * (float)t)) * 0.5f);
    while ((r + 1) * (129 - (r + 1)) / 2 <= t) r++;
    while (r * (129 - r) / 2 > t) r--;
    c = r + (t - r * (129 - r) / 2);
}

// ---------------------------------------------------------------------------
// Persistent tile kernel, 3 CTAs/SM. 128x128 tile processed as two 128x64
// halves with acc=32; row LSE state carried across halves in registers.
// ---------------------------------------------------------------------------
__global__ void __launch_bounds__(256, 3) tile_kernel()
{
    extern __shared__ unsigned char dsm[];
    float2* sRow = (float2*)(dsm + 3 * TILE_SM);          // [128][2] (m,s)
    float2* sCol = (float2*)(dsm + 3 * TILE_SM + 2048);   // [128][4] (m,s)

    int tid  = threadIdx.x;
    int lane = tid & 31;
    int wid  = tid >> 5;
    int wy   = wid >> 1;            // 0..3 (32-row group)
    int wx   = wid & 1;             // 0..1 (32-col group within 64-col half)
    int gid  = lane >> 2;
    int tig  = lane & 3;

    int k  = blockIdx.x;
    int t0 = (int)(((long long)k * NTOT) / GRID_P);
    int t1 = (int)(((long long)(k + 1) * NTOT) / GRID_P);
    int n  = t1 - t0;
    if (n == 0) return;

    uint32_t sAu = smem_u32(dsm);
    uint32_t sB0 = sAu + TILE_SM;
    uint32_t aAddr0 = sAu + (uint32_t)((wy * 32 + (lane & 7) + ((lane >> 3) & 1) * 8) * TROW
                                       + ((lane >> 4) & 1) * 16);
    uint32_t bOff   = (uint32_t)((wx * 32 + ((lane >> 4) & 1) * 8 + (lane & 7)) * TROW
                                 + ((lane >> 3) & 1) * 16);

    auto get_bt = [&](int j, int& b_, int& t_) {
        int g = t0 + j;
        b_ = (g >= NTILE) ? 1 : 0;
        t_ = g - b_ * NTILE;
    };

    int b, t, r, c;
    get_bt(0, b, t);
    decode_tile(t, r, c);

    stage_tile(sAu, g_Y[b], r * 128, tid);
    stage_tile(sB0, g_Y[b], c * 128, tid);
    CP_COMMIT();

    int buf = 0;
    for (int j = 0; j < n; j++) {
        int bn = 0, tn = 0, rn = 0, cn = 0;
        bool have_next = (j + 1 < n);
        if (have_next) { get_bt(j + 1, bn, tn); decode_tile(tn, rn, cn); }

        CP_WAIT0();
        __syncthreads();     // B(cur) staged; prev exports finished reading smem

        if (have_next) {
            uint32_t sBn = sAu + TILE_SM + (uint32_t)((buf ^ 1) * TILE_SM);
            stage_tile(sBn, g_Y[bn], cn * 128, tid);
            CP_COMMIT();
        }

        uint32_t bBase = sAu + TILE_SM + (uint32_t)(buf * TILE_SM) + bOff;
        bool isdiag = (r == c);

        // running row state across the 2 halves: (m, s) per (mf, h)
        float mrun[2][2], srun[2][2];
        #pragma unroll
        for (int mf = 0; mf < 2; mf++)
            #pragma unroll
            for (int h = 0; h < 2; h++) { mrun[mf][h] = -1e30f; srun[mf][h] = 0.f; }

        #pragma unroll
        for (int hf = 0; hf < 2; hf++) {
            float acc[2][4][4];
            #pragma unroll
            for (int mf = 0; mf < 2; mf++)
                #pragma unroll
                for (int nf = 0; nf < 4; nf++)
                    #pragma unroll
                    for (int jj = 0; jj < 4; jj++) acc[mf][nf][jj] = 0.f;

            mainloop_half(acc, aAddr0, bBase + (uint32_t)(hf * 64 * TROW));

            if (isdiag) {
                #pragma unroll
                for (int mf = 0; mf < 2; mf++)
                    #pragma unroll
                    for (int nf = 0; nf < 4; nf++)
                        #pragma unroll
                        for (int jj = 0; jj < 4; jj++) {
                            int rl = wy * 32 + mf * 16 + ((jj >> 1) & 1) * 8 + gid;
                            int cl = hf * 64 + wx * 32 + nf * 8 + tig * 2 + (jj & 1);
                            if (rl == cl) acc[mf][nf][jj] = -1e30f;
                        }
            }

            if (b == 0) {
                // ---- user: fixed basis, single exp pass ----
                #pragma unroll
                for (int mf = 0; mf < 2; mf++)
                    #pragma unroll
                    for (int nf = 0; nf < 4; nf++)
                        #pragma unroll
                        for (int jj = 0; jj < 4; jj++)
                            acc[mf][nf][jj] = ex2(acc[mf][nf][jj] - UBASE);

                #pragma unroll
                for (int mf = 0; mf < 2; mf++)
                    #pragma unroll
                    for (int h = 0; h < 2; h++) {
                        float v = 0.f;
                        #pragma unroll
                        for (int nf = 0; nf < 4; nf++)
                            v += acc[mf][nf][h * 2] + acc[mf][nf][h * 2 + 1];
                        v += __shfl_xor_sync(0xffffffffu, v, 1);
                        v += __shfl_xor_sync(0xffffffffu, v, 2);
                        srun[mf][h] += v;
                        mrun[mf][h] = UBASE;
                    }
                if (!isdiag) {
                    #pragma unroll
                    for (int nf = 0; nf < 4; nf++)
                        #pragma unroll
                        for (int q = 0; q < 2; q++) {
                            float v = 0.f;
                            #pragma unroll
                            for (int mf = 0; mf < 2; mf++)
                                #pragma unroll
                                for (int h = 0; h < 2; h++)
                                    v += acc[mf][nf][h * 2 + q];
                            v += __shfl_xor_sync(0xffffffffu, v, 4);
                            v += __shfl_xor_sync(0xffffffffu, v, 8);
                            v += __shfl_xor_sync(0xffffffffu, v, 16);
                            if (gid == 0)
                                sCol[(hf * 64 + wx * 32 + nf * 8 + tig * 2 + q) * 4 + wy]
                                    = make_float2(UBASE, v);
                        }
                }
            } else {
                // ---- item: warp-local row basis (online across halves) ----
                #pragma unroll
                for (int mf = 0; mf < 2; mf++)
                    #pragma unroll
                    for (int h = 0; h < 2; h++) {
                        float mx = -1e30f;
                        #pragma unroll
                        for (int nf = 0; nf < 4; nf++)
                            mx = fmaxf(mx, fmaxf(acc[mf][nf][h * 2],
                                                 acc[mf][nf][h * 2 + 1]));
                        mx = fmaxf(mx, __shfl_xor_sync(0xffffffffu, mx, 1));
                        mx = fmaxf(mx, __shfl_xor_sync(0xffffffffu, mx, 2));
                        float v = 0.f;
                        #pragma unroll
                        for (int nf = 0; nf < 4; nf++)
                            v += ex2(acc[mf][nf][h * 2] - mx)
                               + ex2(acc[mf][nf][h * 2 + 1] - mx);
                        v += __shfl_xor_sync(0xffffffffu, v, 1);
                        v += __shfl_xor_sync(0xffffffffu, v, 2);
                        float mn = fmaxf(mrun[mf][h], mx);
                        srun[mf][h] = srun[mf][h] * ex2(mrun[mf][h] - mn)
                                    + v * ex2(mx - mn);
                        mrun[mf][h] = mn;
                    }
                // ---- item col partials: per 32-row warp group ----
                if (!isdiag) {
                    #pragma unroll
                    for (int nf = 0; nf < 4; nf++)
                        #pragma unroll
                        for (int q = 0; q < 2; q++) {
                            float mx = -1e30f;
                            #pragma unroll
                            for (int mf = 0; mf < 2; mf++)
                                #pragma unroll
                                for (int h = 0; h < 2; h++)
                                    mx = fmaxf(mx, acc[mf][nf][h * 2 + q]);
                            mx = fmaxf(mx, __shfl_xor_sync(0xffffffffu, mx, 4));
                            mx = fmaxf(mx, __shfl_xor_sync(0xffffffffu, mx, 8));
                            mx = fmaxf(mx, __shfl_xor_sync(0xffffffffu, mx, 16));
                            float v = 0.f;
                            #pragma unroll
                            for (int mf = 0; mf < 2; mf++)
                                #pragma unroll
                                for (int h = 0; h < 2; h++)
                                    v += ex2(acc[mf][nf][h * 2 + q] - mx);
                            v += __shfl_xor_sync(0xffffffffu, v, 4);
                            v += __shfl_xor_sync(0xffffffffu, v, 8);
                            v += __shfl_xor_sync(0xffffffffu, v, 16);
                            if (gid == 0)
                                sCol[(hf * 64 + wx * 32 + nf * 8 + tig * 2 + q) * 4 + wy]
                                    = make_float2(mx, v);
                        }
                }
            }
        }

        // write row state (one sRow slot per wx), then single merge sync
        if (tig == 0) {
            #pragma unroll
            for (int mf = 0; mf < 2; mf++)
                #pragma unroll
                for (int h = 0; h < 2; h++)
                    sRow[(wy * 32 + mf * 16 + h * 8 + gid) * 2 + wx]
                        = make_float2(mrun[mf][h], srun[mf][h]);
        }
        __syncthreads();     // smem reads (mainloop) + merge data ready

        if (have_next && (bn != b || rn != r)) {
            stage_tile(sAu, g_Y[bn], rn * 128, tid);
            CP_COMMIT();
        }

        if (tid < 128) {
            // row export: exact merge of 2 wx partials
            float2 p0 = sRow[tid * 2], p1 = sRow[tid * 2 + 1];
            float M = fmaxf(p0.x, p1.x);
            float S = p0.y * ex2(p0.x - M) + p1.y * ex2(p1.x - M);
            g_mv[b][r][c][tid] = M;
            g_s[b][r][c][tid]  = S;
            if (!isdiag) {
                // col export: two 64-row halves (wy{0,1}, wy{2,3})
                float2 c0 = sCol[tid * 4],     c1 = sCol[tid * 4 + 1];
                float2 c2 = sCol[tid * 4 + 2], c3 = sCol[tid * 4 + 3];
                float M0 = fmaxf(c0.x, c1.x);
                float S0 = c0.y * ex2(c0.x - M0) + c1.y * ex2(c1.x - M0);
                float M1 = fmaxf(c2.x, c3.x);
                float S1 = c2.y * ex2(c2.x - M1) + c3.y * ex2(c3.x - M1);
                g_mv[b][c][64 + 2 * r][tid]     = M0;
                g_s[b][c][64 + 2 * r][tid]      = S0;
                g_mv[b][c][64 + 2 * r + 1][tid] = M1;
                g_s[b][c][64 + 2 * r + 1][tid]  = S1;
            }
        }

        b = bn; t = tn; r = rn; c = cn;
        buf ^= 1;
    }
}

// ---------------------------------------------------------------------------
// Combine + fused finalize: per (b, r, row) merge row-side [r,64) and
// col-side [64, 64+2r) partials exactly.
// ---------------------------------------------------------------------------
__global__ void __launch_bounds__(128) combine_kernel(float* __restrict__ out)
{
    int b   = blockIdx.x >> 6;
    int rt  = blockIdx.x & 63;
    int tid = threadIdx.x;
    __shared__ float sOut[4];
    __shared__ int sLast;

    float m = -1e30f, s = 0.f;
    for (int ct = rt; ct < 64; ct++) {
        float mc = g_mv[b][rt][ct][tid];
        float sc = g_s[b][rt][ct][tid];
        float mn = fmaxf(m, mc);
        s = s * ex2(m - mn) + sc * ex2(mc - mn);
        m = mn;
    }
    for (int idx = 64; idx < 64 + 2 * rt; idx++) {
        float mc = g_mv[b][rt][idx][tid];
        float sc = g_s[b][rt][idx][tid];
        float mn = fmaxf(m, mc);
        s = s * ex2(m - mn) + sc * ex2(mc - mn);
        m = mn;
    }
    float lse = LN2F * (m + lg2(s));
    #pragma unroll
    for (int o = 16; o; o >>= 1) lse += __shfl_xor_sync(0xffffffffu, lse, o);
    if ((tid & 31) == 0) sOut[tid >> 5] = lse;
    __syncthreads();
    if (tid == 0) {
        g_lse_partial[blockIdx.x] = sOut[0] + sOut[1] + sOut[2] + sOut[3];
        __threadfence();
        int old = atomicAdd(&g_count, 1);
        sLast = (old == CMB_BLOCKS - 1) ? 1 : 0;
    }
    __syncthreads();

    if (sLast) {
        __threadfence();
        float v = g_lse_partial[tid] * (1.0f / (float)B2);
        for (int i = tid; i < PREP_BLOCKS; i += 128)
            v -= g_pos_partial[i] * (1.0f / ((float)BATCH * 0.2f));
        #pragma unroll
        for (int o = 16; o; o >>= 1) v += __shfl_xor_sync(0xffffffffu, v, o);
        __shared__ float sF[4];
        if ((tid & 31) == 0) sF[tid >> 5] = v;
        __syncthreads();
        if (tid == 0) {
            out[0] = sF[0] + sF[1] + sF[2] + sF[3];
            g_count = 0;
        }
    }
}

extern "C" void kernel_launch(void* const* d_in, const int* in_sizes, int n_in,
                              void* d_out, int out_size)
{
    const int*   u_list = (const int*)  d_in[0];
    const int*   i_list = (const int*)  d_in[1];
    const float* u1     = (const float*)d_in[2];
    const float* i1     = (const float*)d_in[3];
    const float* u2     = (const float*)d_in[4];
    const float* i2     = (const float*)d_in[5];
    float* out = (float*)d_out;

    cudaFuncSetAttribute(tile_kernel, cudaFuncAttributeMaxDynamicSharedMemorySize,
                         SMEM_REQ);

    prep_kernel<<<PREP_BLOCKS, 256>>>(u_list, i_list, u1, i1, u2, i2);
    tile_kernel<<<GRID_P, 256, SMEM_REQ>>>();
    combine_kernel<<<CMB_BLOCKS, 128>>>(out);
}

// round 13
// speedup vs baseline: 1.3780x; 1.3780x over previous
#include <cuda_runtime.h>
#include <cuda_bf16.h>
#include <math.h>
#include <stdint.h>

#define BATCH 4096
#define B2    8192
#define NTILE 2080                  // triangular 128x128 tiles per branch
#define NTOT  (2 * NTILE)           // 4160
#define LSE_BLOCKS 128
#define PREP_BLOCKS 1024
#define GRID_P 296                  // persistent CTAs (2/SM)
#define LN2F 0.6931471805599453f
#define ROOT_S 2.68579135f          // sqrt(log2(e)/T) folded into operands
#define UBASE 8.0f                  // user-branch fixed basis (logits +-7.22)

#define TROW 144                    // 128B row + 16B pad
#define TILE_SM (128 * TROW)        // 18432 B
#define SMEM_RED 6144
#define SMEM_REQ (3 * TILE_SM + SMEM_RED)   // 61440 B

__device__ __align__(256) __nv_bfloat16 g_Y[2][B2 * 64];  // hi-only rows (128B)
__device__ float g_s[2][64][64][128];
__device__ float g_mv[2][64][64][128];
__device__ float g_lse_partial[LSE_BLOCKS];
__device__ float g_pos_partial[PREP_BLOCKS];
__device__ int   g_count = 0;

// ---------------------------------------------------------------------------
__device__ __forceinline__ uint32_t smem_u32(const void* p) {
    uint32_t a;
    asm("{ .reg .u64 t; cvta.to.shared.u64 t, %1; cvt.u32.u64 %0, t; }" : "=r"(a) : "l"(p));
    return a;
}
__device__ __forceinline__ float ex2(float x) {
    float y; asm("ex2.approx.f32 %0, %1;" : "=f"(y) : "f"(x)); return y;
}
__device__ __forceinline__ float lg2(float x) {
    float y; asm("lg2.approx.f32 %0, %1;" : "=f"(y) : "f"(x)); return y;
}
// pack (a -> low half, b -> high half); unambiguous via mov.b32 vector order
__device__ __forceinline__ uint32_t packh2(float a, float b) {
    uint32_t r;
    asm("{\n\t.reg .b16 lo, hi;\n\t"
        "cvt.rn.f16.f32 lo, %1;\n\t"
        "cvt.rn.f16.f32 hi, %2;\n\t"
        "mov.b32 %0, {lo, hi};\n\t}" : "=r"(r) : "f"(a), "f"(b));
    return r;
}
__device__ __forceinline__ float2 unpackh2(uint32_t v) {
    float2 f;
    asm("{\n\t.reg .b16 lo, hi;\n\t"
        "mov.b32 {lo, hi}, %2;\n\t"
        "cvt.f32.f16 %0, lo;\n\t"
        "cvt.f32.f16 %1, hi;\n\t}" : "=f"(f.x), "=f"(f.y) : "r"(v));
    return f;
}
__device__ __forceinline__ uint32_t ex2h2(uint32_t v) {
    uint32_t r; asm("ex2.approx.f16x2 %0, %1;" : "=r"(r) : "r"(v)); return r;
}
__device__ __forceinline__ uint32_t haddh2(uint32_t a, uint32_t b) {
    uint32_t r; asm("add.rn.f16x2 %0, %1, %2;" : "=r"(r) : "r"(a), "r"(b)); return r;
}
__device__ __forceinline__ void ldsm4(uint32_t* r, uint32_t addr) {
    asm volatile("ldmatrix.sync.aligned.m8n8.x4.shared.b16 {%0,%1,%2,%3}, [%4];"
        : "=r"(r[0]), "=r"(r[1]), "=r"(r[2]), "=r"(r[3]) : "r"(addr));
}
__device__ __forceinline__ void mma16816(float* c, const uint32_t* a,
                                         uint32_t b0, uint32_t b1) {
    asm volatile("mma.sync.aligned.m16n8k16.row.col.f32.bf16.bf16.f32 "
        "{%0,%1,%2,%3}, {%4,%5,%6,%7}, {%8,%9}, {%0,%1,%2,%3};"
        : "+f"(c[0]), "+f"(c[1]), "+f"(c[2]), "+f"(c[3])
        : "r"(a[0]), "r"(a[1]), "r"(a[2]), "r"(a[3]), "r"(b0), "r"(b1));
}
#define CP16(dst, src) \
    asm volatile("cp.async.cg.shared.global [%0], [%1], 16;" :: "r"(dst), "l"(src))
#define CP_COMMIT() asm volatile("cp.async.commit_group;" ::: "memory")
#define CP_WAIT0()  asm volatile("cp.async.wait_group 0;" ::: "memory")

// ---------------------------------------------------------------------------
// Prep (unchanged from R11)
// ---------------------------------------------------------------------------
__global__ void __launch_bounds__(256) prep_kernel(
    const int* __restrict__ u_list, const int* __restrict__ i_list,
    const float* __restrict__ u1t, const float* __restrict__ i1t,
    const float* __restrict__ u2t, const float* __restrict__ i2t)
{
    int w      = blockIdx.x * 8 + (threadIdx.x >> 5);
    int lane   = threadIdx.x & 31;
    int branch = w >> 12;
    int i      = w & (BATCH - 1);

    int idx = (branch ? i_list : u_list)[i];
    const float* t1 = branch ? i1t : u1t;
    const float* t2 = branch ? i2t : u2t;

    float2 a = ((const float2*)(t1 + (size_t)idx * 64))[lane];
    float2 b = ((const float2*)(t2 + (size_t)idx * 64))[lane];

    if (branch == 0) {
        float na = a.x * a.x + a.y * a.y;
        float nb = b.x * b.x + b.y * b.y;
        #pragma unroll
        for (int o = 16; o; o >>= 1) {
            na += __shfl_xor_sync(0xffffffffu, na, o);
            nb += __shfl_xor_sync(0xffffffffu, nb, o);
        }
        float ia = rsqrtf(na), ib = rsqrtf(nb);
        a.x *= ia; a.y *= ia;
        b.x *= ib; b.y *= ib;
    }

    float pd = a.x * b.x + a.y * b.y;
    #pragma unroll
    for (int o = 16; o; o >>= 1) pd += __shfl_xor_sync(0xffffffffu, pd, o);

    __nv_bfloat16* Y = g_Y[branch];
    #pragma unroll
    for (int which = 0; which < 2; which++) {
        float2 v = which ? b : a;
        int row  = which ? (BATCH + i) : i;
        __nv_bfloat16 hx = __float2bfloat16(v.x * ROOT_S);
        __nv_bfloat16 hy = __float2bfloat16(v.y * ROOT_S);
        ((__nv_bfloat162*)(Y + (size_t)row * 64))[lane] = __nv_bfloat162(hx, hy);
    }

    __shared__ float sp_[8];
    if (lane == 0) sp_[threadIdx.x >> 5] = pd;
    __syncthreads();
    if (threadIdx.x == 0) {
        float s = 0.f;
        #pragma unroll
        for (int k = 0; k < 8; k++) s += sp_[k];
        g_pos_partial[blockIdx.x] = s;
    }
}

// ---------------------------------------------------------------------------
__device__ __forceinline__ void stage_tile(uint32_t sdst,
                                           const __nv_bfloat16* __restrict__ Y,
                                           int row0, int tid)
{
    #pragma unroll
    for (int i = 0; i < 4; i++) {
        int l   = i * 256 + tid;
        int row = l >> 3;
        int col = l & 7;
        uint32_t dst = sdst + (uint32_t)(row * TROW + col * 16);
        const char* src = (const char*)(Y + (size_t)(row0 + row) * 64) + col * 16;
        CP16(dst, src);
    }
}

// hi*hi mainloop: warp tile 32m x 64n, acc[mf(2)][nf(8)][4].
__device__ __forceinline__ void mainloop(float acc[2][8][4],
                                         uint32_t aAddr, uint32_t bAddr)
{
    #pragma unroll
    for (int kk = 0; kk < 4; kk++) {
        uint32_t ah[2][4];
        ldsm4(ah[0], aAddr + kk * 32);
        ldsm4(ah[1], aAddr + 16 * TROW + kk * 32);
        #pragma unroll
        for (int ng = 0; ng < 4; ng++) {
            uint32_t bh[4];
            ldsm4(bh, bAddr + ng * 16 * TROW + kk * 32);
            #pragma unroll
            for (int mf = 0; mf < 2; mf++) {
                mma16816(acc[mf][ng * 2],     ah[mf], bh[0], bh[1]);
                mma16816(acc[mf][ng * 2 + 1], ah[mf], bh[2], bh[3]);
            }
        }
    }
}

__device__ __forceinline__ void decode_tile(int t, int& r, int& c)
{
    r = (int)((129.0f - sqrtf(16641.0f - 8.0f * (float)t)) * 0.5f);
    while ((r + 1) * (129 - (r + 1)) / 2 <= t) r++;
    while (r * (129 - r) / 2 > t) r--;
    c = r + (t - r * (129 - r) / 2);
}

// ---------------------------------------------------------------------------
// Persistent tile kernel (R11 structure); epilogues use f16x2 exponentials.
// ---------------------------------------------------------------------------
__global__ void __launch_bounds__(256, 2) tile_kernel()
{
    extern __shared__ unsigned char dsm[];
    float* sRowM = (float*)(dsm + 3 * TILE_SM);          // [128][2]
    float* sColM = (float*)(dsm + 3 * TILE_SM + 1024);   // [128][4]
    float* sRowS = (float*)(dsm + 3 * TILE_SM + 3072);   // [128][2]
    float* sColS = (float*)(dsm + 3 * TILE_SM + 4096);   // [128][4]

    int tid  = threadIdx.x;
    int lane = tid & 31;
    int wid  = tid >> 5;
    int wy   = wid >> 1;
    int wx   = wid & 1;
    int gid  = lane >> 2;
    int tig  = lane & 3;

    int k  = blockIdx.x;
    int t0 = (int)(((long long)k * NTOT) / GRID_P);
    int t1 = (int)(((long long)(k + 1) * NTOT) / GRID_P);
    int n  = t1 - t0;
    if (n == 0) return;

    uint32_t sAu = smem_u32(dsm);
    uint32_t sB0 = sAu + TILE_SM;
    uint32_t aAddr0 = sAu + (uint32_t)((wy * 32 + (lane & 7) + ((lane >> 3) & 1) * 8) * TROW
                                       + ((lane >> 4) & 1) * 16);
    uint32_t bOff   = (uint32_t)((wx * 64 + ((lane >> 4) & 1) * 8 + (lane & 7)) * TROW
                                 + ((lane >> 3) & 1) * 16);

    auto get_bt = [&](int j, int& b_, int& t_) {
        int g = t0 + j;
        b_ = (g >= NTILE) ? 1 : 0;
        t_ = g - b_ * NTILE;
    };

    int b, t, r, c;
    get_bt(0, b, t);
    decode_tile(t, r, c);

    stage_tile(sAu, g_Y[b], r * 128, tid);
    stage_tile(sB0, g_Y[b], c * 128, tid);
    CP_COMMIT();

    int buf = 0;
    for (int j = 0; j < n; j++) {
        int bn = 0, tn = 0, rn = 0, cn = 0;
        bool have_next = (j + 1 < n);
        if (have_next) { get_bt(j + 1, bn, tn); decode_tile(tn, rn, cn); }

        CP_WAIT0();
        __syncthreads();

        if (have_next) {
            uint32_t sBn = sAu + TILE_SM + (uint32_t)((buf ^ 1) * TILE_SM);
            stage_tile(sBn, g_Y[bn], cn * 128, tid);
            CP_COMMIT();
        }

        uint32_t bAddr = sAu + TILE_SM + (uint32_t)(buf * TILE_SM) + bOff;

        float acc[2][8][4];
        #pragma unroll
        for (int mf = 0; mf < 2; mf++)
            #pragma unroll
            for (int nf = 0; nf < 8; nf++)
                #pragma unroll
                for (int jj = 0; jj < 4; jj++) acc[mf][nf][jj] = 0.f;

        mainloop(acc, aAddr0, bAddr);

        __syncthreads();

        if (have_next && (bn != b || rn != r)) {
            stage_tile(sAu, g_Y[bn], rn * 128, tid);
            CP_COMMIT();
        }

        bool isdiag = (r == c);
        if (isdiag) {
            #pragma unroll
            for (int mf = 0; mf < 2; mf++)
                #pragma unroll
                for (int nf = 0; nf < 8; nf++)
                    #pragma unroll
                    for (int jj = 0; jj < 4; jj++) {
                        int rl = wy * 32 + mf * 16 + ((jj >> 1) & 1) * 8 + gid;
                        int cl = wx * 64 + nf * 8 + tig * 2 + (jj & 1);
                        if (rl == cl) acc[mf][nf][jj] = -1e30f;
                    }
        }

        if (b == 0) {
            // ---- user: fixed basis; f16x2 exps, pairs = (q0, q1) ----
            uint32_t E[2][8][2];
            #pragma unroll
            for (int mf = 0; mf < 2; mf++)
                #pragma unroll
                for (int nf = 0; nf < 8; nf++)
                    #pragma unroll
                    for (int h = 0; h < 2; h++)
                        E[mf][nf][h] = ex2h2(packh2(acc[mf][nf][h * 2]     - UBASE,
                                                    acc[mf][nf][h * 2 + 1] - UBASE));
            // row sums per (mf, h): tree over nf, then lo+hi
            #pragma unroll
            for (int mf = 0; mf < 2; mf++)
                #pragma unroll
                for (int h = 0; h < 2; h++) {
                    uint32_t s01 = haddh2(E[mf][0][h], E[mf][1][h]);
                    uint32_t s23 = haddh2(E[mf][2][h], E[mf][3][h]);
                    uint32_t s45 = haddh2(E[mf][4][h], E[mf][5][h]);
                    uint32_t s67 = haddh2(E[mf][6][h], E[mf][7][h]);
                    uint32_t sa  = haddh2(haddh2(s01, s23), haddh2(s45, s67));
                    float2 f = unpackh2(sa);
                    float v = f.x + f.y;
                    v += __shfl_xor_sync(0xffffffffu, v, 1);
                    v += __shfl_xor_sync(0xffffffffu, v, 2);
                    if (tig == 0)
                        sRowS[(wy * 32 + mf * 16 + h * 8 + gid) * 2 + wx] = v;
                }
            // col sums per nf: tree over (mf, h) keeping (q0, q1) lanes
            if (!isdiag) {
                #pragma unroll
                for (int nf = 0; nf < 8; nf++) {
                    uint32_t sq = haddh2(haddh2(E[0][nf][0], E[0][nf][1]),
                                         haddh2(E[1][nf][0], E[1][nf][1]));
                    sq = haddh2(sq, __shfl_xor_sync(0xffffffffu, sq, 4));
                    sq = haddh2(sq, __shfl_xor_sync(0xffffffffu, sq, 8));
                    sq = haddh2(sq, __shfl_xor_sync(0xffffffffu, sq, 16));
                    if (gid == 0) {
                        float2 f = unpackh2(sq);
                        int base = wx * 64 + nf * 8 + tig * 2;
                        sColS[base * 4 + wy]       = f.x;
                        sColS[(base + 1) * 4 + wy] = f.y;
                    }
                }
            }
            __syncthreads();
            if (tid < 128) {
                g_s[0][r][c][tid]  = sRowS[tid * 2] + sRowS[tid * 2 + 1];
                g_mv[0][r][c][tid] = UBASE;
                if (!isdiag) {
                    g_s[0][c][r][tid]  = sColS[tid * 4] + sColS[tid * 4 + 1]
                                       + sColS[tid * 4 + 2] + sColS[tid * 4 + 3];
                    g_mv[0][c][r][tid] = UBASE;
                }
            }
            __syncthreads();
        } else {
            // ---- item row pass: per-(mf,h) basis, f16x2 exps ----
            #pragma unroll
            for (int mf = 0; mf < 2; mf++)
                #pragma unroll
                for (int h = 0; h < 2; h++) {
                    float mx = -1e30f;
                    #pragma unroll
                    for (int nf = 0; nf < 8; nf++)
                        mx = fmaxf(mx, fmaxf(acc[mf][nf][h * 2],
                                             acc[mf][nf][h * 2 + 1]));
                    mx = fmaxf(mx, __shfl_xor_sync(0xffffffffu, mx, 1));
                    mx = fmaxf(mx, __shfl_xor_sync(0xffffffffu, mx, 2));
                    uint32_t p[8];
                    #pragma unroll
                    for (int nf = 0; nf < 8; nf++)
                        p[nf] = ex2h2(packh2(acc[mf][nf][h * 2]     - mx,
                                             acc[mf][nf][h * 2 + 1] - mx));
                    uint32_t sa = haddh2(haddh2(haddh2(p[0], p[1]), haddh2(p[2], p[3])),
                                         haddh2(haddh2(p[4], p[5]), haddh2(p[6], p[7])));
                    float2 f = unpackh2(sa);
                    float v = f.x + f.y;
                    v += __shfl_xor_sync(0xffffffffu, v, 1);
                    v += __shfl_xor_sync(0xffffffffu, v, 2);
                    if (tig == 0) {
                        int row = wy * 32 + mf * 16 + h * 8 + gid;
                        sRowM[row * 2 + wx] = mx;
                        sRowS[row * 2 + wx] = v;
                    }
                }
            // ---- item col pass: per-(nf,q) bases, f16x2 exps ----
            if (!isdiag) {
                #pragma unroll
                for (int nf = 0; nf < 8; nf++) {
                    float c0 = fmaxf(fmaxf(acc[0][nf][0], acc[0][nf][2]),
                                     fmaxf(acc[1][nf][0], acc[1][nf][2]));
                    float c1 = fmaxf(fmaxf(acc[0][nf][1], acc[0][nf][3]),
                                     fmaxf(acc[1][nf][1], acc[1][nf][3]));
                    c0 = fmaxf(c0, __shfl_xor_sync(0xffffffffu, c0, 4));
                    c0 = fmaxf(c0, __shfl_xor_sync(0xffffffffu, c0, 8));
                    c0 = fmaxf(c0, __shfl_xor_sync(0xffffffffu, c0, 16));
                    c1 = fmaxf(c1, __shfl_xor_sync(0xffffffffu, c1, 4));
                    c1 = fmaxf(c1, __shfl_xor_sync(0xffffffffu, c1, 8));
                    c1 = fmaxf(c1, __shfl_xor_sync(0xffffffffu, c1, 16));
                    uint32_t sq = haddh2(
                        haddh2(ex2h2(packh2(acc[0][nf][0] - c0, acc[0][nf][1] - c1)),
                               ex2h2(packh2(acc[0][nf][2] - c0, acc[0][nf][3] - c1))),
                        haddh2(ex2h2(packh2(acc[1][nf][0] - c0, acc[1][nf][1] - c1)),
                               ex2h2(packh2(acc[1][nf][2] - c0, acc[1][nf][3] - c1))));
                    sq = haddh2(sq, __shfl_xor_sync(0xffffffffu, sq, 4));
                    sq = haddh2(sq, __shfl_xor_sync(0xffffffffu, sq, 8));
                    sq = haddh2(sq, __shfl_xor_sync(0xffffffffu, sq, 16));
                    if (gid == 0) {
                        float2 f = unpackh2(sq);
                        int base = wx * 64 + nf * 8 + tig * 2;
                        sColM[base * 4 + wy]       = c0;
                        sColS[base * 4 + wy]       = f.x;
                        sColM[(base + 1) * 4 + wy] = c1;
                        sColS[(base + 1) * 4 + wy] = f.y;
                    }
                }
            }
            __syncthreads();
            if (tid < 128) {
                // merge 2 row partials (different bases) exactly
                float m0 = sRowM[tid * 2], m1 = sRowM[tid * 2 + 1];
                float M = fmaxf(m0, m1);
                g_s[1][r][c][tid]  = sRowS[tid * 2] * ex2(m0 - M)
                                   + sRowS[tid * 2 + 1] * ex2(m1 - M);
                g_mv[1][r][c][tid] = M;
                if (!isdiag) {
                    float cm0 = sColM[tid * 4],     cm1 = sColM[tid * 4 + 1];
                    float cm2 = sColM[tid * 4 + 2], cm3 = sColM[tid * 4 + 3];
                    float CM = fmaxf(fmaxf(cm0, cm1), fmaxf(cm2, cm3));
                    g_s[1][c][r][tid]  = sColS[tid * 4]     * ex2(cm0 - CM)
                                       + sColS[tid * 4 + 1] * ex2(cm1 - CM)
                                       + sColS[tid * 4 + 2] * ex2(cm2 - CM)
                                       + sColS[tid * 4 + 3] * ex2(cm3 - CM);
                    g_mv[1][c][r][tid] = CM;
                }
            }
            __syncthreads();
        }

        b = bn; t = tn; r = rn; c = cn;
        buf ^= 1;
    }
}

// ---------------------------------------------------------------------------
// Combine + fused finalize (unchanged from R11).
// ---------------------------------------------------------------------------
__global__ void __launch_bounds__(128) combine_kernel(float* __restrict__ out)
{
    int b   = blockIdx.x >> 6;
    int rt  = blockIdx.x & 63;
    int tid = threadIdx.x;
    __shared__ float sOut[4];
    __shared__ int sLast;

    float m = -1e30f, s = 0.f;
    #pragma unroll 8
    for (int ct = 0; ct < 64; ct++) {
        float mc = g_mv[b][rt][ct][tid];
        float sc = g_s[b][rt][ct][tid];
        float mn = fmaxf(m, mc);
        s = s * ex2(m - mn) + sc * ex2(mc - mn);
        m = mn;
    }
    float lse = LN2F * (m + lg2(s));
    #pragma unroll
    for (int o = 16; o; o >>= 1) lse += __shfl_xor_sync(0xffffffffu, lse, o);
    if ((tid & 31) == 0) sOut[tid >> 5] = lse;
    __syncthreads();
    if (tid == 0) {
        g_lse_partial[blockIdx.x] = sOut[0] + sOut[1] + sOut[2] + sOut[3];
        __threadfence();
        int old = atomicAdd(&g_count, 1);
        sLast = (old == LSE_BLOCKS - 1) ? 1 : 0;
    }
    __syncthreads();

    if (sLast) {
        __threadfence();
        float v = g_lse_partial[tid] * (1.0f / (float)B2);
        for (int i = tid; i < PREP_BLOCKS; i += 128)
            v -= g_pos_partial[i] * (1.0f / ((float)BATCH * 0.2f));
        #pragma unroll
        for (int o = 16; o; o >>= 1) v += __shfl_xor_sync(0xffffffffu, v, o);
        __shared__ float sF[4];
        if ((tid & 31) == 0) sF[tid >> 5] = v;
        __syncthreads();
        if (tid == 0) {
            out[0] = sF[0] + sF[1] + sF[2] + sF[3];
            g_count = 0;
        }
    }
}

extern "C" void kernel_launch(void* const* d_in, const int* in_sizes, int n_in,
                              void* d_out, int out_size)
{
    const int*   u_list = (const int*)  d_in[0];
    const int*   i_list = (const int*)  d_in[1];
    const float* u1     = (const float*)d_in[2];
    const float* i1     = (const float*)d_in[3];
    const float* u2     = (const float*)d_in[4];
    const float* i2     = (const float*)d_in[5];
    float* out = (float*)d_out;

    cudaFuncSetAttribute(tile_kernel, cudaFuncAttributeMaxDynamicSharedMemorySize,
                         SMEM_REQ);

    prep_kernel<<<PREP_BLOCKS, 256>>>(u_list, i_list, u1, i1, u2, i2);
    tile_kernel<<<GRID_P, 256, SMEM_REQ>>>();
    combine_kernel<<<LSE_BLOCKS, 128>>>(out);
}

// round 14
// speedup vs baseline: 1.4192x; 1.0298x over previous
#include <cuda_runtime.h>
#include <cuda_bf16.h>
#include <math.h>
#include <stdint.h>

#define BATCH 4096
#define B2    8192
#define NTILE 2080                  // triangular 128x128 tiles per branch
#define LSE_BLOCKS 128
#define PREP_BLOCKS 1024
#define GRID_P 296                  // persistent CTAs (2/SM)
#define WU 5                        // user tile weight
#define WI 6                        // item tile weight (heavier epilogue)
#define WTOT (NTILE * (WU + WI))
#define LN2F 0.6931471805599453f
#define ROOT_S 2.68579135f          // sqrt(log2(e)/T) folded into operands
#define UBASE 8.0f                  // user-branch fixed basis (logits +-7.22)

#define TROW 144                    // 128B row + 16B pad
#define TILE_SM (128 * TROW)        // 18432 B
#define SMEM_RED 6144
#define SMEM_REQ (3 * TILE_SM + SMEM_RED)   // 61440 B

__device__ __align__(256) __nv_bfloat16 g_Y[2][B2 * 64];  // hi-only rows (128B)
__device__ float g_s[2][64][64][128];
__device__ float g_mv[2][64][64][128];
__device__ float g_lse_partial[LSE_BLOCKS];
__device__ float g_pos_partial[PREP_BLOCKS];
__device__ int   g_count = 0;

// ---------------------------------------------------------------------------
__device__ __forceinline__ uint32_t smem_u32(const void* p) {
    uint32_t a;
    asm("{ .reg .u64 t; cvta.to.shared.u64 t, %1; cvt.u32.u64 %0, t; }" : "=r"(a) : "l"(p));
    return a;
}
__device__ __forceinline__ float ex2(float x) {
    float y; asm("ex2.approx.f32 %0, %1;" : "=f"(y) : "f"(x)); return y;
}
__device__ __forceinline__ float lg2(float x) {
    float y; asm("lg2.approx.f32 %0, %1;" : "=f"(y) : "f"(x)); return y;
}
__device__ __forceinline__ uint32_t packh2(float a, float b) {
    uint32_t r;
    asm("{\n\t.reg .b16 lo, hi;\n\t"
        "cvt.rn.f16.f32 lo, %1;\n\t"
        "cvt.rn.f16.f32 hi, %2;\n\t"
        "mov.b32 %0, {lo, hi};\n\t}" : "=r"(r) : "f"(a), "f"(b));
    return r;
}
__device__ __forceinline__ float2 unpackh2(uint32_t v) {
    float2 f;
    asm("{\n\t.reg .b16 lo, hi;\n\t"
        "mov.b32 {lo, hi}, %2;\n\t"
        "cvt.f32.f16 %0, lo;\n\t"
        "cvt.f32.f16 %1, hi;\n\t}" : "=f"(f.x), "=f"(f.y) : "r"(v));
    return f;
}
__device__ __forceinline__ uint32_t ex2h2(uint32_t v) {
    uint32_t r; asm("ex2.approx.f16x2 %0, %1;" : "=r"(r) : "r"(v)); return r;
}
__device__ __forceinline__ uint32_t haddh2(uint32_t a, uint32_t b) {
    uint32_t r; asm("add.rn.f16x2 %0, %1, %2;" : "=r"(r) : "r"(a), "r"(b)); return r;
}
__device__ __forceinline__ void ldsm4(uint32_t* r, uint32_t addr) {
    asm volatile("ldmatrix.sync.aligned.m8n8.x4.shared.b16 {%0,%1,%2,%3}, [%4];"
        : "=r"(r[0]), "=r"(r[1]), "=r"(r[2]), "=r"(r[3]) : "r"(addr));
}
__device__ __forceinline__ void mma16816(float* c, const uint32_t* a,
                                         uint32_t b0, uint32_t b1) {
    asm volatile("mma.sync.aligned.m16n8k16.row.col.f32.bf16.bf16.f32 "
        "{%0,%1,%2,%3}, {%4,%5,%6,%7}, {%8,%9}, {%0,%1,%2,%3};"
        : "+f"(c[0]), "+f"(c[1]), "+f"(c[2]), "+f"(c[3])
        : "r"(a[0]), "r"(a[1]), "r"(a[2]), "r"(a[3]), "r"(b0), "r"(b1));
}
#define CP16(dst, src) \
    asm volatile("cp.async.cg.shared.global [%0], [%1], 16;" :: "r"(dst), "l"(src))
#define CP_COMMIT() asm volatile("cp.async.commit_group;" ::: "memory")
#define CP_WAIT0()  asm volatile("cp.async.wait_group 0;" ::: "memory")

// ---------------------------------------------------------------------------
// Prep (unchanged)
// ---------------------------------------------------------------------------
__global__ void __launch_bounds__(256) prep_kernel(
    const int* __restrict__ u_list, const int* __restrict__ i_list,
    const float* __restrict__ u1t, const float* __restrict__ i1t,
    const float* __restrict__ u2t, const float* __restrict__ i2t)
{
    int w      = blockIdx.x * 8 + (threadIdx.x >> 5);
    int lane   = threadIdx.x & 31;
    int branch = w >> 12;
    int i      = w & (BATCH - 1);

    int idx = (branch ? i_list : u_list)[i];
    const float* t1 = branch ? i1t : u1t;
    const float* t2 = branch ? i2t : u2t;

    float2 a = ((const float2*)(t1 + (size_t)idx * 64))[lane];
    float2 b = ((const float2*)(t2 + (size_t)idx * 64))[lane];

    if (branch == 0) {
        float na = a.x * a.x + a.y * a.y;
        float nb = b.x * b.x + b.y * b.y;
        #pragma unroll
        for (int o = 16; o; o >>= 1) {
            na += __shfl_xor_sync(0xffffffffu, na, o);
            nb += __shfl_xor_sync(0xffffffffu, nb, o);
        }
        float ia = rsqrtf(na), ib = rsqrtf(nb);
        a.x *= ia; a.y *= ia;
        b.x *= ib; b.y *= ib;
    }

    float pd = a.x * b.x + a.y * b.y;
    #pragma unroll
    for (int o = 16; o; o >>= 1) pd += __shfl_xor_sync(0xffffffffu, pd, o);

    __nv_bfloat16* Y = g_Y[branch];
    #pragma unroll
    for (int which = 0; which < 2; which++) {
        float2 v = which ? b : a;
        int row  = which ? (BATCH + i) : i;
        __nv_bfloat16 hx = __float2bfloat16(v.x * ROOT_S);
        __nv_bfloat16 hy = __float2bfloat16(v.y * ROOT_S);
        ((__nv_bfloat162*)(Y + (size_t)row * 64))[lane] = __nv_bfloat162(hx, hy);
    }

    __shared__ float sp_[8];
    if (lane == 0) sp_[threadIdx.x >> 5] = pd;
    __syncthreads();
    if (threadIdx.x == 0) {
        float s = 0.f;
        #pragma unroll
        for (int k = 0; k < 8; k++) s += sp_[k];
        g_pos_partial[blockIdx.x] = s;
    }
}

// ---------------------------------------------------------------------------
__device__ __forceinline__ void stage_tile(uint32_t sdst,
                                           const __nv_bfloat16* __restrict__ Y,
                                           int row0, int tid)
{
    #pragma unroll
    for (int i = 0; i < 4; i++) {
        int l   = i * 256 + tid;
        int row = l >> 3;
        int col = l & 7;
        uint32_t dst = sdst + (uint32_t)(row * TROW + col * 16);
        const char* src = (const char*)(Y + (size_t)(row0 + row) * 64) + col * 16;
        CP16(dst, src);
    }
}

__device__ __forceinline__ void mainloop(float acc[2][8][4],
                                         uint32_t aAddr, uint32_t bAddr)
{
    #pragma unroll
    for (int kk = 0; kk < 4; kk++) {
        uint32_t ah[2][4];
        ldsm4(ah[0], aAddr + kk * 32);
        ldsm4(ah[1], aAddr + 16 * TROW + kk * 32);
        #pragma unroll
        for (int ng = 0; ng < 4; ng++) {
            uint32_t bh[4];
            ldsm4(bh, bAddr + ng * 16 * TROW + kk * 32);
            #pragma unroll
            for (int mf = 0; mf < 2; mf++) {
                mma16816(acc[mf][ng * 2],     ah[mf], bh[0], bh[1]);
                mma16816(acc[mf][ng * 2 + 1], ah[mf], bh[2], bh[3]);
            }
        }
    }
}

__device__ __forceinline__ void decode_tile(int t, int& r, int& c)
{
    r = (int)((129.0f - sqrtf(16641.0f - 8.0f * (float)t)) * 0.5f);
    while ((r + 1) * (129 - (r + 1)) / 2 <= t) r++;
    while (r * (129 - r) / 2 > t) r--;
    c = r + (t - r * (129 - r) / 2);
}

// ---------------------------------------------------------------------------
// Persistent tile kernel: weighted split (user 5 : item 6); minimal syncs.
// ---------------------------------------------------------------------------
__global__ void __launch_bounds__(256, 2) tile_kernel()
{
    extern __shared__ unsigned char dsm[];
    float* sRowM = (float*)(dsm + 3 * TILE_SM);          // [128][2]
    float* sColM = (float*)(dsm + 3 * TILE_SM + 1024);   // [128][4]
    float* sRowS = (float*)(dsm + 3 * TILE_SM + 3072);   // [128][2]
    float* sColS = (float*)(dsm + 3 * TILE_SM + 4096);   // [128][4]

    int tid  = threadIdx.x;
    int lane = tid & 31;
    int wid  = tid >> 5;
    int wy   = wid >> 1;
    int wx   = wid & 1;
    int gid  = lane >> 2;
    int tig  = lane & 3;

    // weighted chunk [wlo, whi)
    int k   = blockIdx.x;
    int wlo = (int)(((long long)k * WTOT) / GRID_P);
    int whi = (int)(((long long)(k + 1) * WTOT) / GRID_P);
    int u0 = (wlo + WU - 1) / WU, u1 = (whi + WU - 1) / WU;
    if (u1 > NTILE) u1 = NTILE;
    if (u0 > u1) u0 = u1;
    int lo = wlo - NTILE * WU; if (lo < 0) lo = 0;
    int hi = whi - NTILE * WU; if (hi < 0) hi = 0;
    int i0 = (lo + WI - 1) / WI, i1 = (hi + WI - 1) / WI;
    if (i1 > NTILE) i1 = NTILE;
    if (i0 > i1) i0 = i1;
    int nu = u1 - u0, ni = i1 - i0;
    int n = nu + ni;
    if (n == 0) return;

    uint32_t sAu = smem_u32(dsm);
    uint32_t sB0 = sAu + TILE_SM;
    uint32_t aAddr0 = sAu + (uint32_t)((wy * 32 + (lane & 7) + ((lane >> 3) & 1) * 8) * TROW
                                       + ((lane >> 4) & 1) * 16);
    uint32_t bOff   = (uint32_t)((wx * 64 + ((lane >> 4) & 1) * 8 + (lane & 7)) * TROW
                                 + ((lane >> 3) & 1) * 16);

    auto get_bt = [&](int j, int& b_, int& t_) {
        if (j < nu) { b_ = 0; t_ = u0 + j; }
        else        { b_ = 1; t_ = i0 + (j - nu); }
    };

    int b, t, r, c;
    get_bt(0, b, t);
    decode_tile(t, r, c);

    stage_tile(sAu, g_Y[b], r * 128, tid);
    stage_tile(sB0, g_Y[b], c * 128, tid);
    CP_COMMIT();

    int buf = 0;
    for (int j = 0; j < n; j++) {
        int bn = 0, tn = 0, rn = 0, cn = 0;
        bool have_next = (j + 1 < n);
        if (have_next) { get_bt(j + 1, bn, tn); decode_tile(tn, rn, cn); }

        CP_WAIT0();
        __syncthreads();            // staged data visible; prior exports done

        if (have_next) {
            uint32_t sBn = sAu + TILE_SM + (uint32_t)((buf ^ 1) * TILE_SM);
            stage_tile(sBn, g_Y[bn], cn * 128, tid);
            CP_COMMIT();
        }

        uint32_t bAddr = sAu + TILE_SM + (uint32_t)(buf * TILE_SM) + bOff;

        float acc[2][8][4];
        #pragma unroll
        for (int mf = 0; mf < 2; mf++)
            #pragma unroll
            for (int nf = 0; nf < 8; nf++)
                #pragma unroll
                for (int jj = 0; jj < 4; jj++) acc[mf][nf][jj] = 0.f;

        mainloop(acc, aAddr0, bAddr);

        // A restage only on row change: uniform condition, conditional sync
        bool restageA = have_next && (bn != b || rn != r);
        if (restageA) {
            __syncthreads();        // all warps done reading A smem
            stage_tile(sAu, g_Y[bn], rn * 128, tid);
            CP_COMMIT();
        }

        bool isdiag = (r == c);
        if (isdiag) {
            #pragma unroll
            for (int mf = 0; mf < 2; mf++)
                #pragma unroll
                for (int nf = 0; nf < 8; nf++)
                    #pragma unroll
                    for (int jj = 0; jj < 4; jj++) {
                        int rl = wy * 32 + mf * 16 + ((jj >> 1) & 1) * 8 + gid;
                        int cl = wx * 64 + nf * 8 + tig * 2 + (jj & 1);
                        if (rl == cl) acc[mf][nf][jj] = -1e30f;
                    }
        }

        if (b == 0) {
            // ---- user: fixed basis; f16x2 exps, pairs = (q0, q1) ----
            uint32_t E[2][8][2];
            #pragma unroll
            for (int mf = 0; mf < 2; mf++)
                #pragma unroll
                for (int nf = 0; nf < 8; nf++)
                    #pragma unroll
                    for (int h = 0; h < 2; h++)
                        E[mf][nf][h] = ex2h2(packh2(acc[mf][nf][h * 2]     - UBASE,
                                                    acc[mf][nf][h * 2 + 1] - UBASE));
            #pragma unroll
            for (int mf = 0; mf < 2; mf++)
                #pragma unroll
                for (int h = 0; h < 2; h++) {
                    uint32_t s01 = haddh2(E[mf][0][h], E[mf][1][h]);
                    uint32_t s23 = haddh2(E[mf][2][h], E[mf][3][h]);
                    uint32_t s45 = haddh2(E[mf][4][h], E[mf][5][h]);
                    uint32_t s67 = haddh2(E[mf][6][h], E[mf][7][h]);
                    uint32_t sa  = haddh2(haddh2(s01, s23), haddh2(s45, s67));
                    float2 f = unpackh2(sa);
                    float v = f.x + f.y;
                    v += __shfl_xor_sync(0xffffffffu, v, 1);
                    v += __shfl_xor_sync(0xffffffffu, v, 2);
                    if (tig == 0)
                        sRowS[(wy * 32 + mf * 16 + h * 8 + gid) * 2 + wx] = v;
                }
            if (!isdiag) {
                #pragma unroll
                for (int nf = 0; nf < 8; nf++) {
                    uint32_t sq = haddh2(haddh2(E[0][nf][0], E[0][nf][1]),
                                         haddh2(E[1][nf][0], E[1][nf][1]));
                    sq = haddh2(sq, __shfl_xor_sync(0xffffffffu, sq, 4));
                    sq = haddh2(sq, __shfl_xor_sync(0xffffffffu, sq, 8));
                    sq = haddh2(sq, __shfl_xor_sync(0xffffffffu, sq, 16));
                    if (gid == 0) {
                        float2 f = unpackh2(sq);
                        int base = wx * 64 + nf * 8 + tig * 2;
                        sColS[base * 4 + wy]       = f.x;
                        sColS[(base + 1) * 4 + wy] = f.y;
                    }
                }
            }
            __syncthreads();        // epilogue smem ready for export
            if (tid < 128) {
                g_s[0][r][c][tid]  = sRowS[tid * 2] + sRowS[tid * 2 + 1];
                g_mv[0][r][c][tid] = UBASE;
                if (!isdiag) {
                    g_s[0][c][r][tid]  = sColS[tid * 4] + sColS[tid * 4 + 1]
                                       + sColS[tid * 4 + 2] + sColS[tid * 4 + 3];
                    g_mv[0][c][r][tid] = UBASE;
                }
            }
        } else {
            // ---- item row pass ----
            #pragma unroll
            for (int mf = 0; mf < 2; mf++)
                #pragma unroll
                for (int h = 0; h < 2; h++) {
                    float mx = -1e30f;
                    #pragma unroll
                    for (int nf = 0; nf < 8; nf++)
                        mx = fmaxf(mx, fmaxf(acc[mf][nf][h * 2],
                                             acc[mf][nf][h * 2 + 1]));
                    mx = fmaxf(mx, __shfl_xor_sync(0xffffffffu, mx, 1));
                    mx = fmaxf(mx, __shfl_xor_sync(0xffffffffu, mx, 2));
                    uint32_t p[8];
                    #pragma unroll
                    for (int nf = 0; nf < 8; nf++)
                        p[nf] = ex2h2(packh2(acc[mf][nf][h * 2]     - mx,
                                             acc[mf][nf][h * 2 + 1] - mx));
                    uint32_t sa = haddh2(haddh2(haddh2(p[0], p[1]), haddh2(p[2], p[3])),
                                         haddh2(haddh2(p[4], p[5]), haddh2(p[6], p[7])));
                    float2 f = unpackh2(sa);
                    float v = f.x + f.y;
                    v += __shfl_xor_sync(0xffffffffu, v, 1);
                    v += __shfl_xor_sync(0xffffffffu, v, 2);
                    if (tig == 0) {
                        int row = wy * 32 + mf * 16 + h * 8 + gid;
                        sRowM[row * 2 + wx] = mx;
                        sRowS[row * 2 + wx] = v;
                    }
                }
            // ---- item col pass ----
            if (!isdiag) {
                #pragma unroll
                for (int nf = 0; nf < 8; nf++) {
                    float c0 = fmaxf(fmaxf(acc[0][nf][0], acc[0][nf][2]),
                                     fmaxf(acc[1][nf][0], acc[1][nf][2]));
                    float c1 = fmaxf(fmaxf(acc[0][nf][1], acc[0][nf][3]),
                                     fmaxf(acc[1][nf][1], acc[1][nf][3]));
                    c0 = fmaxf(c0, __shfl_xor_sync(0xffffffffu, c0, 4));
                    c0 = fmaxf(c0, __shfl_xor_sync(0xffffffffu, c0, 8));
                    c0 = fmaxf(c0, __shfl_xor_sync(0xffffffffu, c0, 16));
                    c1 = fmaxf(c1, __shfl_xor_sync(0xffffffffu, c1, 4));
                    c1 = fmaxf(c1, __shfl_xor_sync(0xffffffffu, c1, 8));
                    c1 = fmaxf(c1, __shfl_xor_sync(0xffffffffu, c1, 16));
                    uint32_t sq = haddh2(
                        haddh2(ex2h2(packh2(acc[0][nf][0] - c0, acc[0][nf][1] - c1)),
                               ex2h2(packh2(acc[0][nf][2] - c0, acc[0][nf][3] - c1))),
                        haddh2(ex2h2(packh2(acc[1][nf][0] - c0, acc[1][nf][1] - c1)),
                               ex2h2(packh2(acc[1][nf][2] - c0, acc[1][nf][3] - c1))));
                    sq = haddh2(sq, __shfl_xor_sync(0xffffffffu, sq, 4));
                    sq = haddh2(sq, __shfl_xor_sync(0xffffffffu, sq, 8));
                    sq = haddh2(sq, __shfl_xor_sync(0xffffffffu, sq, 16));
                    if (gid == 0) {
                        float2 f = unpackh2(sq);
                        int base = wx * 64 + nf * 8 + tig * 2;
                        sColM[base * 4 + wy]       = c0;
                        sColS[base * 4 + wy]       = f.x;
                        sColM[(base + 1) * 4 + wy] = c1;
                        sColS[(base + 1) * 4 + wy] = f.y;
                    }
                }
            }
            __syncthreads();        // epilogue smem ready for export
            if (tid < 128) {
                float m0 = sRowM[tid * 2], m1 = sRowM[tid * 2 + 1];
                float M = fmaxf(m0, m1);
                g_s[1][r][c][tid]  = sRowS[tid * 2] * ex2(m0 - M)
                                   + sRowS[tid * 2 + 1] * ex2(m1 - M);
                g_mv[1][r][c][tid] = M;
                if (!isdiag) {
                    float cm0 = sColM[tid * 4],     cm1 = sColM[tid * 4 + 1];
                    float cm2 = sColM[tid * 4 + 2], cm3 = sColM[tid * 4 + 3];
                    float CM = fmaxf(fmaxf(cm0, cm1), fmaxf(cm2, cm3));
                    g_s[1][c][r][tid]  = sColS[tid * 4]     * ex2(cm0 - CM)
                                       + sColS[tid * 4 + 1] * ex2(cm1 - CM)
                                       + sColS[tid * 4 + 2] * ex2(cm2 - CM)
                                       + sColS[tid * 4 + 3] * ex2(cm3 - CM);
                    g_mv[1][c][r][tid] = CM;
                }
            }
        }
        // no trailing sync: next loop-top __syncthreads orders export reads
        // before the following epilogue's smem writes.

        b = bn; t = tn; r = rn; c = cn;
        buf ^= 1;
    }
}

// ---------------------------------------------------------------------------
// Combine + fused finalize: 4 independent (m,s) chains of 16 -> exact merge.
// ---------------------------------------------------------------------------
__global__ void __launch_bounds__(128) combine_kernel(float* __restrict__ out)
{
    int b   = blockIdx.x >> 6;
    int rt  = blockIdx.x & 63;
    int tid = threadIdx.x;
    __shared__ float sOut[4];
    __shared__ int sLast;

    float m[4], s[4];
    #pragma unroll
    for (int q = 0; q < 4; q++) { m[q] = -1e30f; s[q] = 0.f; }

    #pragma unroll 4
    for (int cc = 0; cc < 16; cc++) {
        #pragma unroll
        for (int q = 0; q < 4; q++) {
            int ct = q * 16 + cc;
            float mc = g_mv[b][rt][ct][tid];
            float sc = g_s[b][rt][ct][tid];
            float mn = fmaxf(m[q], mc);
            s[q] = s[q] * ex2(m[q] - mn) + sc * ex2(mc - mn);
            m[q] = mn;
        }
    }
    float M = fmaxf(fmaxf(m[0], m[1]), fmaxf(m[2], m[3]));
    float S = s[0] * ex2(m[0] - M) + s[1] * ex2(m[1] - M)
            + s[2] * ex2(m[2] - M) + s[3] * ex2(m[3] - M);

    float lse = LN2F * (M + lg2(S));
    #pragma unroll
    for (int o = 16; o; o >>= 1) lse += __shfl_xor_sync(0xffffffffu, lse, o);
    if ((tid & 31) == 0) sOut[tid >> 5] = lse;
    __syncthreads();
    if (tid == 0) {
        g_lse_partial[blockIdx.x] = sOut[0] + sOut[1] + sOut[2] + sOut[3];
        __threadfence();
        int old = atomicAdd(&g_count, 1);
        sLast = (old == LSE_BLOCKS - 1) ? 1 : 0;
    }
    __syncthreads();

    if (sLast) {
        __threadfence();
        float v = g_lse_partial[tid] * (1.0f / (float)B2);
        for (int i = tid; i < PREP_BLOCKS; i += 128)
            v -= g_pos_partial[i] * (1.0f / ((float)BATCH * 0.2f));
        #pragma unroll
        for (int o = 16; o; o >>= 1) v += __shfl_xor_sync(0xffffffffu, v, o);
        __shared__ float sF[4];
        if ((tid & 31) == 0) sF[tid >> 5] = v;
        __syncthreads();
        if (tid == 0) {
            out[0] = sF[0] + sF[1] + sF[2] + sF[3];
            g_count = 0;
        }
    }
}

extern "C" void kernel_launch(void* const* d_in, const int* in_sizes, int n_in,
                              void* d_out, int out_size)
{
    const int*   u_list = (const int*)  d_in[0];
    const int*   i_list = (const int*)  d_in[1];
    const float* u1     = (const float*)d_in[2];
    const float* i1     = (const float*)d_in[3];
    const float* u2     = (const float*)d_in[4];
    const float* i2     = (const float*)d_in[5];
    float* out = (float*)d_out;

    cudaFuncSetAttribute(tile_kernel, cudaFuncAttributeMaxDynamicSharedMemorySize,
                         SMEM_REQ);

    prep_kernel<<<PREP_BLOCKS, 256>>>(u_list, i_list, u1, i1, u2, i2);
    tile_kernel<<<GRID_P, 256, SMEM_REQ>>>();
    combine_kernel<<<LSE_BLOCKS, 128>>>(out);
}

// round 16
// speedup vs baseline: 1.5533x; 1.0945x over previous
#include <cuda_runtime.h>
#include <cuda_bf16.h>
#include <math.h>
#include <stdint.h>

#define BATCH 4096
#define B2    8192
#define NTILE 2080                  // triangular 128x128 tiles per branch
#define LSE_BLOCKS 128
#define PREP_BLOCKS 1024
#define GRID_P 296                  // persistent CTAs (2/SM) -- all resident
#define WU 5                        // user tile weight
#define WI 6                        // item tile weight
#define WTOT (NTILE * (WU + WI))
#define LN2F 0.6931471805599453f
#define ROOT_S 2.68579135f          // sqrt(log2(e)/T) folded into operands
#define UBASE 8.0f                  // user-branch fixed basis (logits +-7.22)

#define TROW 144                    // 128B row + 16B pad
#define TILE_SM (128 * TROW)        // 18432 B
#define SMEM_RED 6144
#define SMEM_REQ (3 * TILE_SM + SMEM_RED)   // 61440 B

__device__ __align__(256) __nv_bfloat16 g_Y[2][B2 * 64];  // hi-only rows (128B)
__device__ float2 g_ms[2][64][64][128];     // (m, s) packed partials
__device__ float g_lse_partial[LSE_BLOCKS];
__device__ float g_pos_partial[PREP_BLOCKS];
__device__ int   g_bar1 = 0;                // monotonic ticket barrier
__device__ int   g_count = 0;               // finalize ticket

// ---------------------------------------------------------------------------
__device__ __forceinline__ uint32_t smem_u32(const void* p) {
    uint32_t a;
    asm("{ .reg .u64 t; cvta.to.shared.u64 t, %1; cvt.u32.u64 %0, t; }" : "=r"(a) : "l"(p));
    return a;
}
__device__ __forceinline__ float ex2(float x) {
    float y; asm("ex2.approx.f32 %0, %1;" : "=f"(y) : "f"(x)); return y;
}
__device__ __forceinline__ float lg2(float x) {
    float y; asm("lg2.approx.f32 %0, %1;" : "=f"(y) : "f"(x)); return y;
}
__device__ __forceinline__ uint32_t packh2(float a, float b) {
    uint32_t r;
    asm("{\n\t.reg .b16 lo, hi;\n\t"
        "cvt.rn.f16.f32 lo, %1;\n\t"
        "cvt.rn.f16.f32 hi, %2;\n\t"
        "mov.b32 %0, {lo, hi};\n\t}" : "=r"(r) : "f"(a), "f"(b));
    return r;
}
__device__ __forceinline__ float2 unpackh2(uint32_t v) {
    float2 f;
    asm("{\n\t.reg .b16 lo, hi;\n\t"
        "mov.b32 {lo, hi}, %2;\n\t"
        "cvt.f32.f16 %0, lo;\n\t"
        "cvt.f32.f16 %1, hi;\n\t}" : "=f"(f.x), "=f"(f.y) : "r"(v));
    return f;
}
__device__ __forceinline__ uint32_t ex2h2(uint32_t v) {
    uint32_t r; asm("ex2.approx.f16x2 %0, %1;" : "=r"(r) : "r"(v)); return r;
}
__device__ __forceinline__ uint32_t haddh2(uint32_t a, uint32_t b) {
    uint32_t r; asm("add.rn.f16x2 %0, %1, %2;" : "=r"(r) : "r"(a), "r"(b)); return r;
}
__device__ __forceinline__ void ldsm4(uint32_t* r, uint32_t addr) {
    asm volatile("ldmatrix.sync.aligned.m8n8.x4.shared.b16 {%0,%1,%2,%3}, [%4];"
        : "=r"(r[0]), "=r"(r[1]), "=r"(r[2]), "=r"(r[3]) : "r"(addr));
}
__device__ __forceinline__ void mma16816(float* c, const uint32_t* a,
                                         uint32_t b0, uint32_t b1) {
    asm volatile("mma.sync.aligned.m16n8k16.row.col.f32.bf16.bf16.f32 "
        "{%0,%1,%2,%3}, {%4,%5,%6,%7}, {%8,%9}, {%0,%1,%2,%3};"
        : "+f"(c[0]), "+f"(c[1]), "+f"(c[2]), "+f"(c[3])
        : "r"(a[0]), "r"(a[1]), "r"(a[2]), "r"(a[3]), "r"(b0), "r"(b1));
}
#define CP16(dst, src) \
    asm volatile("cp.async.cg.shared.global [%0], [%1], 16;" :: "r"(dst), "l"(src))
#define CP_COMMIT() asm volatile("cp.async.commit_group;" ::: "memory")
#define CP_WAIT0()  asm volatile("cp.async.wait_group 0;" ::: "memory")

// grid-wide ticket barrier (monotonic counter, graph-replay safe)
__device__ __forceinline__ void grid_barrier(int* ctr) {
    __shared__ int target;
    __syncthreads();
    __threadfence();
    if (threadIdx.x == 0) {
        int t = atomicAdd(ctr, 1);
        target = (t / GRID_P + 1) * GRID_P;
    }
    __syncthreads();
    if (threadIdx.x == 0) {
        volatile int* v = ctr;
        while (*v < target) __nanosleep(64);
    }
    __syncthreads();
    __threadfence();
}

// ---------------------------------------------------------------------------
// Prep (unchanged)
// ---------------------------------------------------------------------------
__global__ void __launch_bounds__(256) prep_kernel(
    const int* __restrict__ u_list, const int* __restrict__ i_list,
    const float* __restrict__ u1t, const float* __restrict__ i1t,
    const float* __restrict__ u2t, const float* __restrict__ i2t)
{
    int w      = blockIdx.x * 8 + (threadIdx.x >> 5);
    int lane   = threadIdx.x & 31;
    int branch = w >> 12;
    int i      = w & (BATCH - 1);

    int idx = (branch ? i_list : u_list)[i];
    const float* t1 = branch ? i1t : u1t;
    const float* t2 = branch ? i2t : u2t;

    float2 a = ((const float2*)(t1 + (size_t)idx * 64))[lane];
    float2 b = ((const float2*)(t2 + (size_t)idx * 64))[lane];

    if (branch == 0) {
        float na = a.x * a.x + a.y * a.y;
        float nb = b.x * b.x + b.y * b.y;
        #pragma unroll
        for (int o = 16; o; o >>= 1) {
            na += __shfl_xor_sync(0xffffffffu, na, o);
            nb += __shfl_xor_sync(0xffffffffu, nb, o);
        }
        float ia = rsqrtf(na), ib = rsqrtf(nb);
        a.x *= ia; a.y *= ia;
        b.x *= ib; b.y *= ib;
    }

    float pd = a.x * b.x + a.y * b.y;
    #pragma unroll
    for (int o = 16; o; o >>= 1) pd += __shfl_xor_sync(0xffffffffu, pd, o);

    __nv_bfloat16* Y = g_Y[branch];
    #pragma unroll
    for (int which = 0; which < 2; which++) {
        float2 v = which ? b : a;
        int row  = which ? (BATCH + i) : i;
        __nv_bfloat16 hx = __float2bfloat16(v.x * ROOT_S);
        __nv_bfloat16 hy = __float2bfloat16(v.y * ROOT_S);
        ((__nv_bfloat162*)(Y + (size_t)row * 64))[lane] = __nv_bfloat162(hx, hy);
    }

    __shared__ float sp_[8];
    if (lane == 0) sp_[threadIdx.x >> 5] = pd;
    __syncthreads();
    if (threadIdx.x == 0) {
        float s = 0.f;
        #pragma unroll
        for (int k = 0; k < 8; k++) s += sp_[k];
        g_pos_partial[blockIdx.x] = s;
    }
}

// ---------------------------------------------------------------------------
__device__ __forceinline__ void stage_tile(uint32_t sdst,
                                           const __nv_bfloat16* __restrict__ Y,
                                           int row0, int tid)
{
    #pragma unroll
    for (int i = 0; i < 4; i++) {
        int l   = i * 256 + tid;
        int row = l >> 3;
        int col = l & 7;
        uint32_t dst = sdst + (uint32_t)(row * TROW + col * 16);
        const char* src = (const char*)(Y + (size_t)(row0 + row) * 64) + col * 16;
        CP16(dst, src);
    }
}

__device__ __forceinline__ void mainloop(float acc[2][8][4],
                                         uint32_t aAddr, uint32_t bAddr)
{
    #pragma unroll
    for (int kk = 0; kk < 4; kk++) {
        uint32_t ah[2][4];
        ldsm4(ah[0], aAddr + kk * 32);
        ldsm4(ah[1], aAddr + 16 * TROW + kk * 32);
        #pragma unroll
        for (int ng = 0; ng < 4; ng++) {
            uint32_t bh[4];
            ldsm4(bh, bAddr + ng * 16 * TROW + kk * 32);
            #pragma unroll
            for (int mf = 0; mf < 2; mf++) {
                mma16816(acc[mf][ng * 2],     ah[mf], bh[0], bh[1]);
                mma16816(acc[mf][ng * 2 + 1], ah[mf], bh[2], bh[3]);
            }
        }
    }
}

__device__ __forceinline__ void decode_tile(int t, int& r, int& c)
{
    r = (int)((129.0f - sqrtf(16641.0f - 8.0f * (float)t)) * 0.5f);
    while ((r + 1) * (129 - (r + 1)) / 2 <= t) r++;
    while (r * (129 - r) / 2 > t) r--;
    c = r + (t - r * (129 - r) / 2);
}

// ---------------------------------------------------------------------------
// Fused persistent kernel: tiles (R14 epilogue) -> grid barrier -> combine.
// ---------------------------------------------------------------------------
__global__ void __launch_bounds__(256, 2) tile_kernel(float* __restrict__ out)
{
    extern __shared__ unsigned char dsm[];
    float* sRowM = (float*)(dsm + 3 * TILE_SM);          // [128][2]
    float* sColM = (float*)(dsm + 3 * TILE_SM + 1024);   // [128][4]
    float* sRowS = (float*)(dsm + 3 * TILE_SM + 3072);   // [128][2]
    float* sColS = (float*)(dsm + 3 * TILE_SM + 4096);   // [128][4]

    int tid  = threadIdx.x;
    int lane = tid & 31;
    int wid  = tid >> 5;
    int wy   = wid >> 1;
    int wx   = wid & 1;
    int gid  = lane >> 2;
    int tig  = lane & 3;

    // weighted chunk [wlo, whi)
    int k   = blockIdx.x;
    int wlo = (int)(((long long)k * WTOT) / GRID_P);
    int whi = (int)(((long long)(k + 1) * WTOT) / GRID_P);
    int u0 = (wlo + WU - 1) / WU, u1 = (whi + WU - 1) / WU;
    if (u1 > NTILE) u1 = NTILE;
    if (u0 > u1) u0 = u1;
    int lo = wlo - NTILE * WU; if (lo < 0) lo = 0;
    int hi = whi - NTILE * WU; if (hi < 0) hi = 0;
    int i0 = (lo + WI - 1) / WI, i1 = (hi + WI - 1) / WI;
    if (i1 > NTILE) i1 = NTILE;
    if (i0 > i1) i0 = i1;
    int nu = u1 - u0, ni = i1 - i0;
    int n = nu + ni;

    uint32_t sAu = smem_u32(dsm);
    uint32_t sB0 = sAu + TILE_SM;
    uint32_t aAddr0 = sAu + (uint32_t)((wy * 32 + (lane & 7) + ((lane >> 3) & 1) * 8) * TROW
                                       + ((lane >> 4) & 1) * 16);
    uint32_t bOff   = (uint32_t)((wx * 64 + ((lane >> 4) & 1) * 8 + (lane & 7)) * TROW
                                 + ((lane >> 3) & 1) * 16);

    auto get_bt = [&](int j, int& b_, int& t_) {
        if (j < nu) { b_ = 0; t_ = u0 + j; }
        else        { b_ = 1; t_ = i0 + (j - nu); }
    };

    if (n > 0) {
        int b, t, r, c;
        get_bt(0, b, t);
        decode_tile(t, r, c);

        stage_tile(sAu, g_Y[b], r * 128, tid);
        stage_tile(sB0, g_Y[b], c * 128, tid);
        CP_COMMIT();

        int buf = 0;
        for (int j = 0; j < n; j++) {
            int bn = 0, tn = 0, rn = 0, cn = 0;
            bool have_next = (j + 1 < n);
            if (have_next) { get_bt(j + 1, bn, tn); decode_tile(tn, rn, cn); }

            CP_WAIT0();
            __syncthreads();        // staged data visible; prior exports done

            if (have_next) {
                uint32_t sBn = sAu + TILE_SM + (uint32_t)((buf ^ 1) * TILE_SM);
                stage_tile(sBn, g_Y[bn], cn * 128, tid);
                CP_COMMIT();
            }

            uint32_t bAddr = sAu + TILE_SM + (uint32_t)(buf * TILE_SM) + bOff;

            float acc[2][8][4];
            #pragma unroll
            for (int mf = 0; mf < 2; mf++)
                #pragma unroll
                for (int nf = 0; nf < 8; nf++)
                    #pragma unroll
                    for (int jj = 0; jj < 4; jj++) acc[mf][nf][jj] = 0.f;

            mainloop(acc, aAddr0, bAddr);

            bool restageA = have_next && (bn != b || rn != r);
            if (restageA) {
                __syncthreads();    // all warps done reading A smem
                stage_tile(sAu, g_Y[bn], rn * 128, tid);
                CP_COMMIT();
            }

            bool isdiag = (r == c);
            if (isdiag) {
                #pragma unroll
                for (int mf = 0; mf < 2; mf++)
                    #pragma unroll
                    for (int nf = 0; nf < 8; nf++)
                        #pragma unroll
                        for (int jj = 0; jj < 4; jj++) {
                            int rl = wy * 32 + mf * 16 + ((jj >> 1) & 1) * 8 + gid;
                            int cl = wx * 64 + nf * 8 + tig * 2 + (jj & 1);
                            if (rl == cl) acc[mf][nf][jj] = -1e30f;
                        }
            }

            if (b == 0) {
                // ---- user: fixed basis; f16x2 exps, pairs = (q0, q1) ----
                uint32_t E[2][8][2];
                #pragma unroll
                for (int mf = 0; mf < 2; mf++)
                    #pragma unroll
                    for (int nf = 0; nf < 8; nf++)
                        #pragma unroll
                        for (int h = 0; h < 2; h++)
                            E[mf][nf][h] = ex2h2(packh2(acc[mf][nf][h * 2]     - UBASE,
                                                        acc[mf][nf][h * 2 + 1] - UBASE));
                #pragma unroll
                for (int mf = 0; mf < 2; mf++)
                    #pragma unroll
                    for (int h = 0; h < 2; h++) {
                        uint32_t s01 = haddh2(E[mf][0][h], E[mf][1][h]);
                        uint32_t s23 = haddh2(E[mf][2][h], E[mf][3][h]);
                        uint32_t s45 = haddh2(E[mf][4][h], E[mf][5][h]);
                        uint32_t s67 = haddh2(E[mf][6][h], E[mf][7][h]);
                        uint32_t sa  = haddh2(haddh2(s01, s23), haddh2(s45, s67));
                        float2 f = unpackh2(sa);
                        float v = f.x + f.y;
                        v += __shfl_xor_sync(0xffffffffu, v, 1);
                        v += __shfl_xor_sync(0xffffffffu, v, 2);
                        if (tig == 0)
                            sRowS[(wy * 32 + mf * 16 + h * 8 + gid) * 2 + wx] = v;
                    }
                if (!isdiag) {
                    #pragma unroll
                    for (int nf = 0; nf < 8; nf++) {
                        uint32_t sq = haddh2(haddh2(E[0][nf][0], E[0][nf][1]),
                                             haddh2(E[1][nf][0], E[1][nf][1]));
                        sq = haddh2(sq, __shfl_xor_sync(0xffffffffu, sq, 4));
                        sq = haddh2(sq, __shfl_xor_sync(0xffffffffu, sq, 8));
                        sq = haddh2(sq, __shfl_xor_sync(0xffffffffu, sq, 16));
                        if (gid == 0) {
                            float2 f = unpackh2(sq);
                            int base = wx * 64 + nf * 8 + tig * 2;
                            sColS[base * 4 + wy]       = f.x;
                            sColS[(base + 1) * 4 + wy] = f.y;
                        }
                    }
                }
                __syncthreads();
                if (tid < 128) {
                    g_ms[0][r][c][tid] = make_float2(
                        UBASE, sRowS[tid * 2] + sRowS[tid * 2 + 1]);
                    if (!isdiag)
                        g_ms[0][c][r][tid] = make_float2(
                            UBASE, sColS[tid * 4] + sColS[tid * 4 + 1]
                                 + sColS[tid * 4 + 2] + sColS[tid * 4 + 3]);
                }
            } else {
                // ---- item row pass: per-(mf,h) bases (SAFE) ----
                #pragma unroll
                for (int mf = 0; mf < 2; mf++)
                    #pragma unroll
                    for (int h = 0; h < 2; h++) {
                        float mx = -1e30f;
                        #pragma unroll
                        for (int nf = 0; nf < 8; nf++)
                            mx = fmaxf(mx, fmaxf(acc[mf][nf][h * 2],
                                                 acc[mf][nf][h * 2 + 1]));
                        mx = fmaxf(mx, __shfl_xor_sync(0xffffffffu, mx, 1));
                        mx = fmaxf(mx, __shfl_xor_sync(0xffffffffu, mx, 2));
                        uint32_t p[8];
                        #pragma unroll
                        for (int nf = 0; nf < 8; nf++)
                            p[nf] = ex2h2(packh2(acc[mf][nf][h * 2]     - mx,
                                                 acc[mf][nf][h * 2 + 1] - mx));
                        uint32_t sa = haddh2(haddh2(haddh2(p[0], p[1]), haddh2(p[2], p[3])),
                                             haddh2(haddh2(p[4], p[5]), haddh2(p[6], p[7])));
                        float2 f = unpackh2(sa);
                        float v = f.x + f.y;
                        v += __shfl_xor_sync(0xffffffffu, v, 1);
                        v += __shfl_xor_sync(0xffffffffu, v, 2);
                        if (tig == 0) {
                            int row = wy * 32 + mf * 16 + h * 8 + gid;
                            sRowM[row * 2 + wx] = mx;
                            sRowS[row * 2 + wx] = v;
                        }
                    }
                // ---- item col pass: per-(nf,q) bases (SAFE) ----
                if (!isdiag) {
                    #pragma unroll
                    for (int nf = 0; nf < 8; nf++) {
                        float c0 = fmaxf(fmaxf(acc[0][nf][0], acc[0][nf][2]),
                                         fmaxf(acc[1][nf][0], acc[1][nf][2]));
                        float c1 = fmaxf(fmaxf(acc[0][nf][1], acc[0][nf][3]),
                                         fmaxf(acc[1][nf][1], acc[1][nf][3]));
                        c0 = fmaxf(c0, __shfl_xor_sync(0xffffffffu, c0, 4));
                        c0 = fmaxf(c0, __shfl_xor_sync(0xffffffffu, c0, 8));
                        c0 = fmaxf(c0, __shfl_xor_sync(0xffffffffu, c0, 16));
                        c1 = fmaxf(c1, __shfl_xor_sync(0xffffffffu, c1, 4));
                        c1 = fmaxf(c1, __shfl_xor_sync(0xffffffffu, c1, 8));
                        c1 = fmaxf(c1, __shfl_xor_sync(0xffffffffu, c1, 16));
                        uint32_t sq = haddh2(
                            haddh2(ex2h2(packh2(acc[0][nf][0] - c0, acc[0][nf][1] - c1)),
                                   ex2h2(packh2(acc[0][nf][2] - c0, acc[0][nf][3] - c1))),
                            haddh2(ex2h2(packh2(acc[1][nf][0] - c0, acc[1][nf][1] - c1)),
                                   ex2h2(packh2(acc[1][nf][2] - c0, acc[1][nf][3] - c1))));
                        sq = haddh2(sq, __shfl_xor_sync(0xffffffffu, sq, 4));
                        sq = haddh2(sq, __shfl_xor_sync(0xffffffffu, sq, 8));
                        sq = haddh2(sq, __shfl_xor_sync(0xffffffffu, sq, 16));
                        if (gid == 0) {
                            float2 f = unpackh2(sq);
                            int base = wx * 64 + nf * 8 + tig * 2;
                            sColM[base * 4 + wy]       = c0;
                            sColS[base * 4 + wy]       = f.x;
                            sColM[(base + 1) * 4 + wy] = c1;
                            sColS[(base + 1) * 4 + wy] = f.y;
                        }
                    }
                }
                __syncthreads();
                if (tid < 128) {
                    float m0 = sRowM[tid * 2], m1 = sRowM[tid * 2 + 1];
                    float M = fmaxf(m0, m1);
                    g_ms[1][r][c][tid] = make_float2(
                        M, sRowS[tid * 2] * ex2(m0 - M)
                         + sRowS[tid * 2 + 1] * ex2(m1 - M));
                    if (!isdiag) {
                        float cm0 = sColM[tid * 4],     cm1 = sColM[tid * 4 + 1];
                        float cm2 = sColM[tid * 4 + 2], cm3 = sColM[tid * 4 + 3];
                        float CM = fmaxf(fmaxf(cm0, cm1), fmaxf(cm2, cm3));
                        g_ms[1][c][r][tid] = make_float2(
                            CM, sColS[tid * 4]     * ex2(cm0 - CM)
                              + sColS[tid * 4 + 1] * ex2(cm1 - CM)
                              + sColS[tid * 4 + 2] * ex2(cm2 - CM)
                              + sColS[tid * 4 + 3] * ex2(cm3 - CM));
                    }
                }
            }
            // no trailing sync: loop-top __syncthreads orders export reads.

            b = bn; t = tn; r = rn; c = cn;
            buf ^= 1;
        }
    }

    // ================= grid barrier, then combine on CTAs 0..127 ===========
    grid_barrier(&g_bar1);

    if (blockIdx.x < LSE_BLOCKS && tid < 128) {
        int b  = blockIdx.x >> 6;
        int rt = blockIdx.x & 63;

        float m[4], s[4];
        #pragma unroll
        for (int q = 0; q < 4; q++) { m[q] = -1e30f; s[q] = 0.f; }
        #pragma unroll 4
        for (int cc = 0; cc < 16; cc++) {
            #pragma unroll
            for (int q = 0; q < 4; q++) {
                float2 p = g_ms[b][rt][q * 16 + cc][tid];
                float mn = fmaxf(m[q], p.x);
                s[q] = s[q] * ex2(m[q] - mn) + p.y * ex2(p.x - mn);
                m[q] = mn;
            }
        }
        float M = fmaxf(fmaxf(m[0], m[1]), fmaxf(m[2], m[3]));
        float S = s[0] * ex2(m[0] - M) + s[1] * ex2(m[1] - M)
                + s[2] * ex2(m[2] - M) + s[3] * ex2(m[3] - M);

        float lse = LN2F * (M + lg2(S));
        #pragma unroll
        for (int o = 16; o; o >>= 1) lse += __shfl_xor_sync(0xffffffffu, lse, o);
        float* sOut = sRowM;       // reuse smem
        if (lane == 0) sOut[wid] = lse;
        __syncwarp();
        // reduce 4 warps (wid 0..3) via smem; wid 0 lane 0 finishes
        __syncthreads();
        __shared__ int sLast;
        if (tid == 0) {
            g_lse_partial[blockIdx.x] = sOut[0] + sOut[1] + sOut[2] + sOut[3];
            __threadfence();
            int old = atomicAdd(&g_count, 1);
            sLast = ((old + 1) % LSE_BLOCKS == 0) ? 1 : 0;
        }
        __syncthreads();
        if (sLast) {
            __threadfence();
            float v = g_lse_partial[tid] * (1.0f / (float)B2);
            for (int i = tid; i < PREP_BLOCKS; i += 128)
                v -= g_pos_partial[i] * (1.0f / ((float)BATCH * 0.2f));
            #pragma unroll
            for (int o = 16; o; o >>= 1) v += __shfl_xor_sync(0xffffffffu, v, o);
            float* sF = sColM;     // reuse smem
            if (lane == 0) sF[wid] = v;
            __syncthreads();
            if (tid == 0) out[0] = sF[0] + sF[1] + sF[2] + sF[3];
        }
    }
}

extern "C" void kernel_launch(void* const* d_in, const int* in_sizes, int n_in,
                              void* d_out, int out_size)
{
    const int*   u_list = (const int*)  d_in[0];
    const int*   i_list = (const int*)  d_in[1];
    const float* u1     = (const float*)d_in[2];
    const float* i1     = (const float*)d_in[3];
    const float* u2     = (const float*)d_in[4];
    const float* i2     = (const float*)d_in[5];
    float* out = (float*)d_out;

    cudaFuncSetAttribute(tile_kernel, cudaFuncAttributeMaxDynamicSharedMemorySize,
                         SMEM_REQ);

    prep_kernel<<<PREP_BLOCKS, 256>>>(u_list, i_list, u1, i1, u2, i2);
    tile_kernel<<<GRID_P, 256, SMEM_REQ>>>(out);
}

// round 17
// speedup vs baseline: 1.5559x; 1.0017x over previous
#include <cuda_runtime.h>
#include <cuda_bf16.h>
#include <math.h>
#include <stdint.h>

#define BATCH 4096
#define B2    8192
#define NTILE 2080                  // triangular 128x128 tiles per branch
#define NCHUNK 2080                 // 2 tiles per chunk, 4160 tiles total
#define LSE_BLOCKS 128
#define PREP_BLOCKS 1024
#define GRID_P 296                  // persistent CTAs (2/SM) -- all resident
#define LN2F 0.6931471805599453f
#define ROOT_S 2.68579135f          // sqrt(log2(e)/T) folded into operands
#define UBASE 8.0f                  // user-branch fixed basis (logits +-7.22)

#define TROW 144                    // 128B row + 16B pad
#define TILE_SM (128 * TROW)        // 18432 B
#define SMEM_RED 6144
#define SMEM_REQ (3 * TILE_SM + SMEM_RED)   // 61440 B

__device__ __align__(256) __nv_bfloat16 g_Y[2][B2 * 64];  // hi-only rows (128B)
__device__ float2 g_ms[2][64][64][128];     // (m, s) packed partials
__device__ float g_lse_partial[LSE_BLOCKS];
__device__ float g_pos_partial[PREP_BLOCKS];
__device__ int   g_bar1 = 0;                // monotonic ticket barrier
__device__ int   g_count = 0;               // finalize ticket (mod LSE_BLOCKS)
__device__ int   g_ticket = 0;              // work-steal counter (reset by prep)

// ---------------------------------------------------------------------------
__device__ __forceinline__ uint32_t smem_u32(const void* p) {
    uint32_t a;
    asm("{ .reg .u64 t; cvta.to.shared.u64 t, %1; cvt.u32.u64 %0, t; }" : "=r"(a) : "l"(p));
    return a;
}
__device__ __forceinline__ float ex2(float x) {
    float y; asm("ex2.approx.f32 %0, %1;" : "=f"(y) : "f"(x)); return y;
}
__device__ __forceinline__ float lg2(float x) {
    float y; asm("lg2.approx.f32 %0, %1;" : "=f"(y) : "f"(x)); return y;
}
__device__ __forceinline__ uint32_t packh2(float a, float b) {
    uint32_t r;
    asm("{\n\t.reg .b16 lo, hi;\n\t"
        "cvt.rn.f16.f32 lo, %1;\n\t"
        "cvt.rn.f16.f32 hi, %2;\n\t"
        "mov.b32 %0, {lo, hi};\n\t}" : "=r"(r) : "f"(a), "f"(b));
    return r;
}
__device__ __forceinline__ float2 unpackh2(uint32_t v) {
    float2 f;
    asm("{\n\t.reg .b16 lo, hi;\n\t"
        "mov.b32 {lo, hi}, %2;\n\t"
        "cvt.f32.f16 %0, lo;\n\t"
        "cvt.f32.f16 %1, hi;\n\t}" : "=f"(f.x), "=f"(f.y) : "r"(v));
    return f;
}
__device__ __forceinline__ uint32_t ex2h2(uint32_t v) {
    uint32_t r; asm("ex2.approx.f16x2 %0, %1;" : "=r"(r) : "r"(v)); return r;
}
__device__ __forceinline__ uint32_t haddh2(uint32_t a, uint32_t b) {
    uint32_t r; asm("add.rn.f16x2 %0, %1, %2;" : "=r"(r) : "r"(a), "r"(b)); return r;
}
__device__ __forceinline__ void ldsm4(uint32_t* r, uint32_t addr) {
    asm volatile("ldmatrix.sync.aligned.m8n8.x4.shared.b16 {%0,%1,%2,%3}, [%4];"
        : "=r"(r[0]), "=r"(r[1]), "=r"(r[2]), "=r"(r[3]) : "r"(addr));
}
__device__ __forceinline__ void mma16816(float* c, const uint32_t* a,
                                         uint32_t b0, uint32_t b1) {
    asm volatile("mma.sync.aligned.m16n8k16.row.col.f32.bf16.bf16.f32 "
        "{%0,%1,%2,%3}, {%4,%5,%6,%7}, {%8,%9}, {%0,%1,%2,%3};"
        : "+f"(c[0]), "+f"(c[1]), "+f"(c[2]), "+f"(c[3])
        : "r"(a[0]), "r"(a[1]), "r"(a[2]), "r"(a[3]), "r"(b0), "r"(b1));
}
#define CP16(dst, src) \
    asm volatile("cp.async.cg.shared.global [%0], [%1], 16;" :: "r"(dst), "l"(src))
#define CP_COMMIT() asm volatile("cp.async.commit_group;" ::: "memory")
#define CP_WAIT0()  asm volatile("cp.async.wait_group 0;" ::: "memory")

// grid-wide ticket barrier (monotonic counter, graph-replay safe)
__device__ __forceinline__ void grid_barrier(int* ctr) {
    __shared__ int target;
    __syncthreads();
    __threadfence();
    if (threadIdx.x == 0) {
        int t = atomicAdd(ctr, 1);
        target = (t / GRID_P + 1) * GRID_P;
    }
    __syncthreads();
    if (threadIdx.x == 0) {
        volatile int* v = ctr;
        while (*v < target) __nanosleep(64);
    }
    __syncthreads();
    __threadfence();
}

// ---------------------------------------------------------------------------
// Prep: gather + normalize + split; resets the work-steal counter.
// ---------------------------------------------------------------------------
__global__ void __launch_bounds__(256) prep_kernel(
    const int* __restrict__ u_list, const int* __restrict__ i_list,
    const float* __restrict__ u1t, const float* __restrict__ i1t,
    const float* __restrict__ u2t, const float* __restrict__ i2t)
{
    if (blockIdx.x == 0 && threadIdx.x == 0) g_ticket = 0;

    int w      = blockIdx.x * 8 + (threadIdx.x >> 5);
    int lane   = threadIdx.x & 31;
    int branch = w >> 12;
    int i      = w & (BATCH - 1);

    int idx = (branch ? i_list : u_list)[i];
    const float* t1 = branch ? i1t : u1t;
    const float* t2 = branch ? i2t : u2t;

    float2 a = ((const float2*)(t1 + (size_t)idx * 64))[lane];
    float2 b = ((const float2*)(t2 + (size_t)idx * 64))[lane];

    if (branch == 0) {
        float na = a.x * a.x + a.y * a.y;
        float nb = b.x * b.x + b.y * b.y;
        #pragma unroll
        for (int o = 16; o; o >>= 1) {
            na += __shfl_xor_sync(0xffffffffu, na, o);
            nb += __shfl_xor_sync(0xffffffffu, nb, o);
        }
        float ia = rsqrtf(na), ib = rsqrtf(nb);
        a.x *= ia; a.y *= ia;
        b.x *= ib; b.y *= ib;
    }

    float pd = a.x * b.x + a.y * b.y;
    #pragma unroll
    for (int o = 16; o; o >>= 1) pd += __shfl_xor_sync(0xffffffffu, pd, o);

    __nv_bfloat16* Y = g_Y[branch];
    #pragma unroll
    for (int which = 0; which < 2; which++) {
        float2 v = which ? b : a;
        int row  = which ? (BATCH + i) : i;
        __nv_bfloat16 hx = __float2bfloat16(v.x * ROOT_S);
        __nv_bfloat16 hy = __float2bfloat16(v.y * ROOT_S);
        ((__nv_bfloat162*)(Y + (size_t)row * 64))[lane] = __nv_bfloat162(hx, hy);
    }

    __shared__ float sp_[8];
    if (lane == 0) sp_[threadIdx.x >> 5] = pd;
    __syncthreads();
    if (threadIdx.x == 0) {
        float s = 0.f;
        #pragma unroll
        for (int k = 0; k < 8; k++) s += sp_[k];
        g_pos_partial[blockIdx.x] = s;
    }
}

// ---------------------------------------------------------------------------
__device__ __forceinline__ void stage_tile(uint32_t sdst,
                                           const __nv_bfloat16* __restrict__ Y,
                                           int row0, int tid)
{
    #pragma unroll
    for (int i = 0; i < 4; i++) {
        int l   = i * 256 + tid;
        int row = l >> 3;
        int col = l & 7;
        uint32_t dst = sdst + (uint32_t)(row * TROW + col * 16);
        const char* src = (const char*)(Y + (size_t)(row0 + row) * 64) + col * 16;
        CP16(dst, src);
    }
}

__device__ __forceinline__ void mainloop(float acc[2][8][4],
                                         uint32_t aAddr, uint32_t bAddr)
{
    #pragma unroll
    for (int kk = 0; kk < 4; kk++) {
        uint32_t ah[2][4];
        ldsm4(ah[0], aAddr + kk * 32);
        ldsm4(ah[1], aAddr + 16 * TROW + kk * 32);
        #pragma unroll
        for (int ng = 0; ng < 4; ng++) {
            uint32_t bh[4];
            ldsm4(bh, bAddr + ng * 16 * TROW + kk * 32);
            #pragma unroll
            for (int mf = 0; mf < 2; mf++) {
                mma16816(acc[mf][ng * 2],     ah[mf], bh[0], bh[1]);
                mma16816(acc[mf][ng * 2 + 1], ah[mf], bh[2], bh[3]);
            }
        }
    }
}

__device__ __forceinline__ void decode_g(int g, int& b_, int& r, int& c)
{
    b_ = (g >= NTILE) ? 1 : 0;
    int t = g - b_ * NTILE;
    r = (int)((129.0f - sqrtf(16641.0f - 8.0f * (float)t)) * 0.5f);
    while ((r + 1) * (129 - (r + 1)) / 2 <= t) r++;
    while (r * (129 - r) / 2 > t) r--;
    c = r + (t - r * (129 - r) / 2);
}

// ---------------------------------------------------------------------------
// Fused persistent kernel: dynamic chunked tickets -> tiles -> barrier ->
// combine. Per-tile math identical to R16.
// ---------------------------------------------------------------------------
__global__ void __launch_bounds__(256, 2) tile_kernel(float* __restrict__ out)
{
    extern __shared__ unsigned char dsm[];
    float* sRowM = (float*)(dsm + 3 * TILE_SM);          // [128][2]
    float* sColM = (float*)(dsm + 3 * TILE_SM + 1024);   // [128][4]
    float* sRowS = (float*)(dsm + 3 * TILE_SM + 3072);   // [128][2]
    float* sColS = (float*)(dsm + 3 * TILE_SM + 4096);   // [128][4]
    __shared__ int sChunk;

    int tid  = threadIdx.x;
    int lane = tid & 31;
    int wid  = tid >> 5;
    int wy   = wid >> 1;
    int wx   = wid & 1;
    int gid  = lane >> 2;
    int tig  = lane & 3;

    uint32_t sAu = smem_u32(dsm);
    uint32_t sB0 = sAu + TILE_SM;
    uint32_t aAddr0 = sAu + (uint32_t)((wy * 32 + (lane & 7) + ((lane >> 3) & 1) * 8) * TROW
                                       + ((lane >> 4) & 1) * 16);
    uint32_t bOff   = (uint32_t)((wx * 64 + ((lane >> 4) & 1) * 8 + (lane & 7)) * TROW
                                 + ((lane >> 3) & 1) * 16);

    // grab first chunk
    if (tid == 0) sChunk = atomicAdd(&g_ticket, 1);
    __syncthreads();
    int chunk = sChunk;

    if (chunk < NCHUNK) {
        int b, r, c;
        decode_g(chunk * 2, b, r, c);

        stage_tile(sAu, g_Y[b], r * 128, tid);
        stage_tile(sB0, g_Y[b], c * 128, tid);
        CP_COMMIT();

        int buf = 0;
        int idx = 0;                 // tile index within chunk (0 or 1)
        for (;;) {
            CP_WAIT0();
            __syncthreads();        // staged data visible; prior exports done;
                                    // also orders sChunk write/read pairs

            int bn = 0, rn = 0, cn = 0;
            int next_chunk = chunk;
            bool have_next;
            if (idx == 0) {
                if (tid == 0) sChunk = atomicAdd(&g_ticket, 1);  // for chunk+1
                decode_g(chunk * 2 + 1, bn, rn, cn);
                have_next = true;
            } else {
                int nc = sChunk;    // posted one tile ago, sync'd since
                if (nc < NCHUNK) { next_chunk = nc; decode_g(nc * 2, bn, rn, cn); have_next = true; }
                else have_next = false;
            }

            if (have_next) {
                uint32_t sBn = sAu + TILE_SM + (uint32_t)((buf ^ 1) * TILE_SM);
                stage_tile(sBn, g_Y[bn], cn * 128, tid);
                CP_COMMIT();
            }

            uint32_t bAddr = sAu + TILE_SM + (uint32_t)(buf * TILE_SM) + bOff;

            float acc[2][8][4];
            #pragma unroll
            for (int mf = 0; mf < 2; mf++)
                #pragma unroll
                for (int nf = 0; nf < 8; nf++)
                    #pragma unroll
                    for (int jj = 0; jj < 4; jj++) acc[mf][nf][jj] = 0.f;

            mainloop(acc, aAddr0, bAddr);

            bool restageA = have_next && (bn != b || rn != r);
            if (restageA) {
                __syncthreads();    // all warps done reading A smem
                stage_tile(sAu, g_Y[bn], rn * 128, tid);
                CP_COMMIT();
            }

            bool isdiag = (r == c);
            if (isdiag) {
                #pragma unroll
                for (int mf = 0; mf < 2; mf++)
                    #pragma unroll
                    for (int nf = 0; nf < 8; nf++)
                        #pragma unroll
                        for (int jj = 0; jj < 4; jj++) {
                            int rl = wy * 32 + mf * 16 + ((jj >> 1) & 1) * 8 + gid;
                            int cl = wx * 64 + nf * 8 + tig * 2 + (jj & 1);
                            if (rl == cl) acc[mf][nf][jj] = -1e30f;
                        }
            }

            if (b == 0) {
                // ---- user: fixed basis; f16x2 exps, pairs = (q0, q1) ----
                uint32_t E[2][8][2];
                #pragma unroll
                for (int mf = 0; mf < 2; mf++)
                    #pragma unroll
                    for (int nf = 0; nf < 8; nf++)
                        #pragma unroll
                        for (int h = 0; h < 2; h++)
                            E[mf][nf][h] = ex2h2(packh2(acc[mf][nf][h * 2]     - UBASE,
                                                        acc[mf][nf][h * 2 + 1] - UBASE));
                #pragma unroll
                for (int mf = 0; mf < 2; mf++)
                    #pragma unroll
                    for (int h = 0; h < 2; h++) {
                        uint32_t s01 = haddh2(E[mf][0][h], E[mf][1][h]);
                        uint32_t s23 = haddh2(E[mf][2][h], E[mf][3][h]);
                        uint32_t s45 = haddh2(E[mf][4][h], E[mf][5][h]);
                        uint32_t s67 = haddh2(E[mf][6][h], E[mf][7][h]);
                        uint32_t sa  = haddh2(haddh2(s01, s23), haddh2(s45, s67));
                        float2 f = unpackh2(sa);
                        float v = f.x + f.y;
                        v += __shfl_xor_sync(0xffffffffu, v, 1);
                        v += __shfl_xor_sync(0xffffffffu, v, 2);
                        if (tig == 0)
                            sRowS[(wy * 32 + mf * 16 + h * 8 + gid) * 2 + wx] = v;
                    }
                if (!isdiag) {
                    #pragma unroll
                    for (int nf = 0; nf < 8; nf++) {
                        uint32_t sq = haddh2(haddh2(E[0][nf][0], E[0][nf][1]),
                                             haddh2(E[1][nf][0], E[1][nf][1]));
                        sq = haddh2(sq, __shfl_xor_sync(0xffffffffu, sq, 4));
                        sq = haddh2(sq, __shfl_xor_sync(0xffffffffu, sq, 8));
                        sq = haddh2(sq, __shfl_xor_sync(0xffffffffu, sq, 16));
                        if (gid == 0) {
                            float2 f = unpackh2(sq);
                            int base = wx * 64 + nf * 8 + tig * 2;
                            sColS[base * 4 + wy]       = f.x;
                            sColS[(base + 1) * 4 + wy] = f.y;
                        }
                    }
                }
                __syncthreads();
                if (tid < 128) {
                    g_ms[0][r][c][tid] = make_float2(
                        UBASE, sRowS[tid * 2] + sRowS[tid * 2 + 1]);
                    if (!isdiag)
                        g_ms[0][c][r][tid] = make_float2(
                            UBASE, sColS[tid * 4] + sColS[tid * 4 + 1]
                                 + sColS[tid * 4 + 2] + sColS[tid * 4 + 3]);
                }
            } else {
                // ---- item row pass: per-(mf,h) bases (SAFE) ----
                #pragma unroll
                for (int mf = 0; mf < 2; mf++)
                    #pragma unroll
                    for (int h = 0; h < 2; h++) {
                        float mx = -1e30f;
                        #pragma unroll
                        for (int nf = 0; nf < 8; nf++)
                            mx = fmaxf(mx, fmaxf(acc[mf][nf][h * 2],
                                                 acc[mf][nf][h * 2 + 1]));
                        mx = fmaxf(mx, __shfl_xor_sync(0xffffffffu, mx, 1));
                        mx = fmaxf(mx, __shfl_xor_sync(0xffffffffu, mx, 2));
                        uint32_t p[8];
                        #pragma unroll
                        for (int nf = 0; nf < 8; nf++)
                            p[nf] = ex2h2(packh2(acc[mf][nf][h * 2]     - mx,
                                                 acc[mf][nf][h * 2 + 1] - mx));
                        uint32_t sa = haddh2(haddh2(haddh2(p[0], p[1]), haddh2(p[2], p[3])),
                                             haddh2(haddh2(p[4], p[5]), haddh2(p[6], p[7])));
                        float2 f = unpackh2(sa);
                        float v = f.x + f.y;
                        v += __shfl_xor_sync(0xffffffffu, v, 1);
                        v += __shfl_xor_sync(0xffffffffu, v, 2);
                        if (tig == 0) {
                            int row = wy * 32 + mf * 16 + h * 8 + gid;
                            sRowM[row * 2 + wx] = mx;
                            sRowS[row * 2 + wx] = v;
                        }
                    }
                // ---- item col pass: per-(nf,q) bases (SAFE) ----
                if (!isdiag) {
                    #pragma unroll
                    for (int nf = 0; nf < 8; nf++) {
                        float c0 = fmaxf(fmaxf(acc[0][nf][0], acc[0][nf][2]),
                                         fmaxf(acc[1][nf][0], acc[1][nf][2]));
                        float c1 = fmaxf(fmaxf(acc[0][nf][1], acc[0][nf][3]),
                                         fmaxf(acc[1][nf][1], acc[1][nf][3]));
                        c0 = fmaxf(c0, __shfl_xor_sync(0xffffffffu, c0, 4));
                        c0 = fmaxf(c0, __shfl_xor_sync(0xffffffffu, c0, 8));
                        c0 = fmaxf(c0, __shfl_xor_sync(0xffffffffu, c0, 16));
                        c1 = fmaxf(c1, __shfl_xor_sync(0xffffffffu, c1, 4));
                        c1 = fmaxf(c1, __shfl_xor_sync(0xffffffffu, c1, 8));
                        c1 = fmaxf(c1, __shfl_xor_sync(0xffffffffu, c1, 16));
                        uint32_t sq = haddh2(
                            haddh2(ex2h2(packh2(acc[0][nf][0] - c0, acc[0][nf][1] - c1)),
                                   ex2h2(packh2(acc[0][nf][2] - c0, acc[0][nf][3] - c1))),
                            haddh2(ex2h2(packh2(acc[1][nf][0] - c0, acc[1][nf][1] - c1)),
                                   ex2h2(packh2(acc[1][nf][2] - c0, acc[1][nf][3] - c1))));
                        sq = haddh2(sq, __shfl_xor_sync(0xffffffffu, sq, 4));
                        sq = haddh2(sq, __shfl_xor_sync(0xffffffffu, sq, 8));
                        sq = haddh2(sq, __shfl_xor_sync(0xffffffffu, sq, 16));
                        if (gid == 0) {
                            float2 f = unpackh2(sq);
                            int base = wx * 64 + nf * 8 + tig * 2;
                            sColM[base * 4 + wy]       = c0;
                            sColS[base * 4 + wy]       = f.x;
                            sColM[(base + 1) * 4 + wy] = c1;
                            sColS[(base + 1) * 4 + wy] = f.y;
                        }
                    }
                }
                __syncthreads();
                if (tid < 128) {
                    float m0 = sRowM[tid * 2], m1 = sRowM[tid * 2 + 1];
                    float M = fmaxf(m0, m1);
                    g_ms[1][r][c][tid] = make_float2(
                        M, sRowS[tid * 2] * ex2(m0 - M)
                         + sRowS[tid * 2 + 1] * ex2(m1 - M));
                    if (!isdiag) {
                        float cm0 = sColM[tid * 4],     cm1 = sColM[tid * 4 + 1];
                        float cm2 = sColM[tid * 4 + 2], cm3 = sColM[tid * 4 + 3];
                        float CM = fmaxf(fmaxf(cm0, cm1), fmaxf(cm2, cm3));
                        g_ms[1][c][r][tid] = make_float2(
                            CM, sColS[tid * 4]     * ex2(cm0 - CM)
                              + sColS[tid * 4 + 1] * ex2(cm1 - CM)
                              + sColS[tid * 4 + 2] * ex2(cm2 - CM)
                              + sColS[tid * 4 + 3] * ex2(cm3 - CM));
                    }
                }
            }
            // no trailing sync: loop-top __syncthreads orders export reads.

            if (!have_next) break;
            b = bn; r = rn; c = cn;
            buf ^= 1;
            idx ^= 1;
            chunk = next_chunk;
        }
    }

    // ================= grid barrier, then combine on CTAs 0..127 ===========
    grid_barrier(&g_bar1);

    if (blockIdx.x < LSE_BLOCKS && tid < 128) {
        int b  = blockIdx.x >> 6;
        int rt = blockIdx.x & 63;

        float m[4], s[4];
        #pragma unroll
        for (int q = 0; q < 4; q++) { m[q] = -1e30f; s[q] = 0.f; }
        #pragma unroll 4
        for (int cc = 0; cc < 16; cc++) {
            #pragma unroll
            for (int q = 0; q < 4; q++) {
                float2 p = g_ms[b][rt][q * 16 + cc][tid];
                float mn = fmaxf(m[q], p.x);
                s[q] = s[q] * ex2(m[q] - mn) + p.y * ex2(p.x - mn);
                m[q] = mn;
            }
        }
        float M = fmaxf(fmaxf(m[0], m[1]), fmaxf(m[2], m[3]));
        float S = s[0] * ex2(m[0] - M) + s[1] * ex2(m[1] - M)
                + s[2] * ex2(m[2] - M) + s[3] * ex2(m[3] - M);

        float lse = LN2F * (M + lg2(S));
        #pragma unroll
        for (int o = 16; o; o >>= 1) lse += __shfl_xor_sync(0xffffffffu, lse, o);
        float* sOut = sRowM;       // reuse smem
        if (lane == 0) sOut[wid] = lse;
        __syncwarp();
        __syncthreads();
        __shared__ int sLast;
        if (tid == 0) {
            g_lse_partial[blockIdx.x] = sOut[0] + sOut[1] + sOut[2] + sOut[3];
            __threadfence();
            int old = atomicAdd(&g_count, 1);
            sLast = ((old + 1) % LSE_BLOCKS == 0) ? 1 : 0;
        }
        __syncthreads();
        if (sLast) {
            __threadfence();
            float v = g_lse_partial[tid] * (1.0f / (float)B2);
            for (int i = tid; i < PREP_BLOCKS; i += 128)
                v -= g_pos_partial[i] * (1.0f / ((float)BATCH * 0.2f));
            #pragma unroll
            for (int o = 16; o; o >>= 1) v += __shfl_xor_sync(0xffffffffu, v, o);
            float* sF = sColM;     // reuse smem
            if (lane == 0) sF[wid] = v;
            __syncthreads();
            if (tid == 0) out[0] = sF[0] + sF[1] + sF[2] + sF[3];
        }
    }
}

extern "C" void kernel_launch(void* const* d_in, const int* in_sizes, int n_in,
                              void* d_out, int out_size)
{
    const int*   u_list = (const int*)  d_in[0];
    const int*   i_list = (const int*)  d_in[1];
    const float* u1     = (const float*)d_in[2];
    const float* i1     = (const float*)d_in[3];
    const float* u2     = (const float*)d_in[4];
    const float* i2     = (const float*)d_in[5];
    float* out = (float*)d_out;

    cudaFuncSetAttribute(tile_kernel, cudaFuncAttributeMaxDynamicSharedMemorySize,
                         SMEM_REQ);

    prep_kernel<<<PREP_BLOCKS, 256>>>(u_list, i_list, u1, i1, u2, i2);
    tile_kernel<<<GRID_P, 256, SMEM_REQ>>>(out);
}